// round 10
// baseline (speedup 1.0000x reference)
#include <cuda_runtime.h>
#include <cuda_bf16.h>
#include <cstdint>

// Swin layer: split-bf16 HMMA QKV GEMM + fused flash-attention + O-proj.
// R10: break MMA accumulator RAW chains (term-outermost issue order).
#define NTOK 131072          // 32 * 64 * 64 tokens

// -------- device scratch (allocation-free rule) --------
__device__ __nv_bfloat16 g_qkvh[(size_t)NTOK * 768];
__device__ __nv_bfloat16 g_qkvl[(size_t)NTOK * 768];
__device__ __nv_bfloat16 g_yh[NTOK * 256];      // pass-1 output, image layout
__device__ __nv_bfloat16 g_yl[NTOK * 256];
__device__ __nv_bfloat16 g_wtq_hi[768 * 256];   // W_qkv^T  [N][K]
__device__ __nv_bfloat16 g_wtq_lo[768 * 256];
__device__ __nv_bfloat16 g_wto_hi[256 * 256];   // W_o^T    [N][K]
__device__ __nv_bfloat16 g_wto_lo[256 * 256];

// ======================= helpers =======================
__device__ __forceinline__ uint32_t smem_u32(const void* p) {
    uint32_t a;
    asm("{ .reg .u64 t; cvta.to.shared.u64 t, %1; cvt.u32.u64 %0, t; }" : "=r"(a) : "l"(p));
    return a;
}
__device__ __forceinline__ void ldsm4(uint32_t r[4], uint32_t addr) {
    asm volatile("ldmatrix.sync.aligned.m8n8.x4.shared.b16 {%0,%1,%2,%3}, [%4];"
                 : "=r"(r[0]), "=r"(r[1]), "=r"(r[2]), "=r"(r[3]) : "r"(addr));
}
__device__ __forceinline__ void ldsm4t(uint32_t r[4], uint32_t addr) {
    asm volatile("ldmatrix.sync.aligned.m8n8.x4.trans.shared.b16 {%0,%1,%2,%3}, [%4];"
                 : "=r"(r[0]), "=r"(r[1]), "=r"(r[2]), "=r"(r[3]) : "r"(addr));
}
__device__ __forceinline__ void mma16816(float d[4], const uint32_t a[4],
                                         uint32_t b0, uint32_t b1) {
    asm volatile(
        "mma.sync.aligned.m16n8k16.row.col.f32.bf16.bf16.f32 "
        "{%0,%1,%2,%3}, {%4,%5,%6,%7}, {%8,%9}, {%0,%1,%2,%3};"
        : "+f"(d[0]), "+f"(d[1]), "+f"(d[2]), "+f"(d[3])
        : "r"(a[0]), "r"(a[1]), "r"(a[2]), "r"(a[3]), "r"(b0), "r"(b1));
}
__device__ __forceinline__ uint32_t pk(float c0, float c1) {   // bf16x2(lo=c0, hi=c1)
    uint32_t d;
    asm("cvt.rn.bf16x2.f32 %0, %1, %2;" : "=r"(d) : "f"(c1), "f"(c0));
    return d;
}
__device__ __forceinline__ float bf16rt(float v) {
    return __bfloat162float(__float2bfloat16(v));
}
__device__ __forceinline__ int regid(int wh, int ww, int t) {
    int r = t >> 3, c = t & 7;
    int hr = (wh == 7) ? ((r < 4) ? 1 : 2) : 0;
    int wr = (ww == 7) ? ((c < 4) ? 1 : 2) : 0;
    return hr * 3 + wr;
}

// ======================= prep: W^T hi/lo split =======================
__global__ void prep_kernel(const float* __restrict__ wqkv, const float* __restrict__ wo) {
    int i = blockIdx.x * blockDim.x + threadIdx.x;
    if (i < 768 * 256) {
        int n = i >> 8, k = i & 255;
        float f = wqkv[k * 768 + n];
        float h = bf16rt(f);
        g_wtq_hi[i] = __float2bfloat16(h);
        g_wtq_lo[i] = __float2bfloat16(f - h);
    } else if (i < 768 * 256 + 256 * 256) {
        int j = i - 768 * 256;
        int n = j >> 8, k = j & 255;
        float f = wo[k * 256 + n];
        float h = bf16rt(f);
        g_wto_hi[j] = __float2bfloat16(h);
        g_wto_lo[j] = __float2bfloat16(f - h);
    }
}

// ======================= QKV GEMM kernel =======================
#define LDA      264
#define A_LO_OFF 67584
#define GB_OFF   135168
#define B_BUF    36864
#define B_HALF   18432
#define LDB_B    144
#define GS_SMEM  (GB_OFF + 2 * B_BUF)

__global__ __launch_bounds__(256, 1)
void gemm_qkv(const float* __restrict__ xin,
              const __nv_bfloat16* __restrict__ yh_in, const __nv_bfloat16* __restrict__ yl_in,
              const __nv_bfloat16* __restrict__ wh, const __nv_bfloat16* __restrict__ wl,
              const float* __restrict__ bias,
              __nv_bfloat16* __restrict__ qh_out, __nv_bfloat16* __restrict__ ql_out,
              int shifted)
{
    extern __shared__ char sb[];
    const uint32_t smb = smem_u32(sb);
    const int tid = threadIdx.x, wid = tid >> 5, lane = tid & 31;
    const int blk = blockIdx.x;
    const int sh = shifted ? 4 : 0;

    // ---- load A (128 rows x 256), window-gather with roll ----
    for (int g = tid; g < 4096; g += 256) {
        int t = g >> 5;
        int col0 = (g & 31) * 8;
        int tok = blk * 128 + t;
        int m = tok >> 12, w = (tok >> 6) & 63, tt = tok & 63;
        int gh = ((w >> 3) * 8 + (tt >> 3) + sh) & 63;
        int gw = ((w & 7) * 8 + (tt & 7) + sh) & 63;
        size_t idx = (size_t)((m * 64 + gh) * 64 + gw) * 256 + col0;
        uint32_t off = ((uint32_t)t * LDA + col0) * 2;
        if (!shifted) {
            const float* sp = xin + idx;
            float4 f0 = *(const float4*)sp, f1 = *(const float4*)(sp + 4);
            float fv[8] = {f0.x, f0.y, f0.z, f0.w, f1.x, f1.y, f1.z, f1.w};
            uint32_t hw[4], lw[4];
#pragma unroll
            for (int q = 0; q < 4; ++q) {
                float h0 = bf16rt(fv[2 * q]), h1 = bf16rt(fv[2 * q + 1]);
                hw[q] = pk(h0, h1);
                lw[q] = pk(fv[2 * q] - h0, fv[2 * q + 1] - h1);
            }
            *(uint4*)(sb + off)            = make_uint4(hw[0], hw[1], hw[2], hw[3]);
            *(uint4*)(sb + A_LO_OFF + off) = make_uint4(lw[0], lw[1], lw[2], lw[3]);
        } else {
            *(uint4*)(sb + off)            = *(const uint4*)(yh_in + idx);
            *(uint4*)(sb + A_LO_OFF + off) = *(const uint4*)(yl_in + idx);
        }
    }

    const int mbase = (wid & 3) * 32;
    const int nbase = (wid >> 2) * 64;
    const int grp = lane >> 3, r8 = lane & 7;
    const int a_row = mbase + r8 + ((grp & 1) << 3);
    const int a_kof = (grp & 2) ? 8 : 0;
    const uint32_t aHi = smb + (uint32_t)(a_row * LDA + a_kof) * 2;
    const uint32_t aLo = aHi + A_LO_OFF;
    const int b_n  = r8 + ((grp & 2) << 2);
    const int b_kof = (grp & 1) ? 8 : 0;
    const uint32_t bBase = smb + GB_OFF + (uint32_t)((nbase + b_n) * 72 + b_kof) * 2;
    const int qr = lane >> 2, qc = (lane & 3) * 2;

    for (int nt = 0; nt < 6; ++nt) {
        float d[2][8][4];
#pragma unroll
        for (int mf = 0; mf < 2; ++mf)
#pragma unroll
            for (int nf = 0; nf < 8; ++nf)
#pragma unroll
                for (int q = 0; q < 4; ++q) d[mf][nf][q] = 0.f;

#pragma unroll
        for (int i = 0; i < 8; ++i) {
            int g = tid + i * 256;
            int half = g >> 10, j = g & 1023;
            int n = j >> 3, kq = j & 7;
            const __nv_bfloat16* W = half ? wl : wh;
            uint4 v = *(const uint4*)(W + (size_t)(nt * 128 + n) * 256 + kq * 8);
            *(uint4*)(sb + GB_OFF + half * B_HALF + n * LDB_B + kq * 16) = v;
        }
        __syncthreads();

        for (int c = 0; c < 4; ++c) {
            uint4 stg[8];
            if (c < 3) {
#pragma unroll
                for (int i = 0; i < 8; ++i) {
                    int g = tid + i * 256;
                    int half = g >> 10, j = g & 1023;
                    int n = j >> 3, kq = j & 7;
                    const __nv_bfloat16* W = half ? wl : wh;
                    stg[i] = *(const uint4*)(W + (size_t)(nt * 128 + n) * 256 + (c + 1) * 64 + kq * 8);
                }
            }
            const uint32_t bb0 = bBase + (uint32_t)(c & 1) * B_BUF;
#pragma unroll
            for (int kk8 = 0; kk8 < 4; ++kk8) {
                const int kg = c * 64 + kk8 * 16;
                uint32_t ah[2][4], al[2][4];
                ldsm4(ah[0], aHi + (uint32_t)kg * 2);
                ldsm4(ah[1], aHi + 16u * (LDA * 2) + (uint32_t)kg * 2);
                ldsm4(al[0], aLo + (uint32_t)kg * 2);
                ldsm4(al[1], aLo + 16u * (LDA * 2) + (uint32_t)kg * 2);
                uint32_t bh[4][4], bl[4][4];
                const uint32_t bb = bb0 + (uint32_t)kk8 * 32;
#pragma unroll
                for (int np = 0; np < 4; ++np) {
                    ldsm4(bh[np], bb + (uint32_t)np * (16 * LDB_B));
                    ldsm4(bl[np], bb + B_HALF + (uint32_t)np * (16 * LDB_B));
                }
                // term-outermost: 16 independent accumulators between reuses
#pragma unroll
                for (int term = 0; term < 3; ++term)
#pragma unroll
                    for (int mf = 0; mf < 2; ++mf)
#pragma unroll
                        for (int nf = 0; nf < 8; ++nf) {
                            const int np = nf >> 1, hv = (nf & 1) * 2;
                            const uint32_t* aa = (term == 2) ? al[mf] : ah[mf];
                            const uint32_t* bv = (term == 1) ? bl[np] : bh[np];
                            mma16816(d[mf][nf], aa, bv[hv], bv[hv + 1]);
                        }
            }
            if (c < 3) {
#pragma unroll
                for (int i = 0; i < 8; ++i) {
                    int g = tid + i * 256;
                    int half = g >> 10, j = g & 1023;
                    int n = j >> 3, kq = j & 7;
                    *(uint4*)(sb + GB_OFF + ((c + 1) & 1) * B_BUF + half * B_HALF + n * LDB_B + kq * 16) = stg[i];
                }
            }
            __syncthreads();
        }

        // ---- epilogue: bias, stage packed words in dead B smem, coalesced store ----
#pragma unroll
        for (int mf = 0; mf < 2; ++mf)
#pragma unroll
            for (int h8 = 0; h8 < 2; ++h8) {
                int row = mbase + mf * 16 + h8 * 8 + qr;
#pragma unroll
                for (int nf = 0; nf < 8; ++nf) {
                    int col = nbase + nf * 8 + qc;
                    float v0 = d[mf][nf][h8 * 2]     + bias[nt * 128 + col];
                    float v1 = d[mf][nf][h8 * 2 + 1] + bias[nt * 128 + col + 1];
                    float h0 = bf16rt(v0), h1 = bf16rt(v1);
                    uint32_t off = (uint32_t)(row * 128 + col) * 2;
                    *(uint32_t*)(sb + GB_OFF + off)         = pk(h0, h1);
                    *(uint32_t*)(sb + GB_OFF + 32768 + off) = pk(v0 - h0, v1 - h1);
                }
            }
        __syncthreads();
#pragma unroll
        for (int i = 0; i < 8; ++i) {
            int g = tid + i * 256;               // 0..2047
            int row = g >> 4, u = g & 15;        // 16 x uint4 per 128-col row
            size_t base = (size_t)(blk * 128 + row) * 768 + nt * 128 + u * 8;
            *(uint4*)(qh_out + base) = *(const uint4*)(sb + GB_OFF + row * 256 + u * 16);
            *(uint4*)(ql_out + base) = *(const uint4*)(sb + GB_OFF + 32768 + row * 256 + u * 16);
        }
        __syncthreads();
    }
}

// ======================= fused attention + O-proj kernel =======================
#define LDQ  264
#define AQH  0
#define AQL  33792
#define AKH  67584
#define AKL  101376
#define AVH  135168
#define AVL  168960
#define OB   67584            // O-proj B staging (overwrites K/V areas)
#define OB_HALF 36864
#define AT_SMEM 202752

__global__ __launch_bounds__(256, 1)
void attn_fused(const __nv_bfloat16* __restrict__ qkvh, const __nv_bfloat16* __restrict__ qkvl,
                const __nv_bfloat16* __restrict__ woh, const __nv_bfloat16* __restrict__ wol,
                const float* __restrict__ bo,
                __nv_bfloat16* __restrict__ yh_out, __nv_bfloat16* __restrict__ yl_out,
                float* __restrict__ f32_out, int shifted)
{
    extern __shared__ char sb[];
    const uint32_t smb = smem_u32(sb);
    const int tid = threadIdx.x, wid = tid >> 5, lane = tid & 31;
    const int win = blockIdx.x;
    const int wh_ = (win & 63) >> 3, ww_ = win & 7;
    const int sh = shifted ? 4 : 0;

    // ---- load pre-split qkv: straight uint4 copies ----
    {
        const int t = tid >> 2;
        const size_t rbase = (size_t)(win * 64 + t) * 768;
#pragma unroll
        for (int i = 0; i < 24; ++i) {
            int col0 = ((tid & 3) + i * 4) * 8;      // 0..760
            int sel = col0 >> 8, c = col0 & 255;
            uint32_t bh = (sel == 0) ? AQH : (sel == 1) ? AKH : AVH;
            uint32_t off = (uint32_t)(t * LDQ + c) * 2;
            *(uint4*)(sb + bh + off)         = *(const uint4*)(qkvh + rbase + col0);
            *(uint4*)(sb + bh + 33792 + off) = *(const uint4*)(qkvl + rbase + col0);
        }
    }
    __syncthreads();

    const int head = wid;
    const int hcol = head * 32;
    const int arow = lane & 15, acolh = (lane >> 4) * 8;
    const int grp = lane >> 3, r8 = lane & 7;
    const int b_n = r8 + ((grp & 2) << 2), b_k = (grp & 1) * 8;
    const int v_k = r8 + ((grp & 1) << 3), v_n = (grp & 2) << 2;
    const int qr = lane >> 2, qc = (lane & 3) * 2;
    const float scale = 0.17677669529663687f;

    int creg[16];
#pragma unroll
    for (int j = 0; j < 8; ++j) {
        creg[2 * j]     = regid(wh_, ww_, j * 8 + qc);
        creg[2 * j + 1] = regid(wh_, ww_, j * 8 + qc + 1);
    }

    for (int mh = 0; mh < 2; ++mh) {
        const int rbase = mh * 32;
        uint32_t qh[2][2][4], ql[2][2][4];
#pragma unroll
        for (int i = 0; i < 2; ++i)
#pragma unroll
            for (int kt = 0; kt < 2; ++kt) {
                uint32_t off = (uint32_t)((rbase + i * 16 + arow) * LDQ + hcol + kt * 16 + acolh) * 2;
                ldsm4(qh[i][kt], smb + AQH + off);
                ldsm4(ql[i][kt], smb + AQL + off);
            }

        float s[2][8][4];
#pragma unroll
        for (int i = 0; i < 2; ++i)
#pragma unroll
            for (int j = 0; j < 8; ++j)
#pragma unroll
                for (int q = 0; q < 4; ++q) s[i][j][q] = 0.f;
#pragma unroll
        for (int kt = 0; kt < 2; ++kt)
#pragma unroll
            for (int ng = 0; ng < 4; ++ng) {
                uint32_t kh4[4], kl4[4];
                uint32_t ka = (uint32_t)((ng * 16 + b_n) * LDQ + hcol + kt * 16 + b_k) * 2;
                ldsm4(kh4, smb + AKH + ka);
                ldsm4(kl4, smb + AKL + ka);
                // term-outermost: 4 independent accumulators between reuses
#pragma unroll
                for (int term = 0; term < 3; ++term)
#pragma unroll
                    for (int i = 0; i < 2; ++i) {
                        const uint32_t* aa = (term == 2) ? ql[i][kt] : qh[i][kt];
                        const uint32_t* bv = (term == 1) ? kl4 : kh4;
                        mma16816(s[i][2 * ng],     aa, bv[0], bv[1]);
                        mma16816(s[i][2 * ng + 1], aa, bv[2], bv[3]);
                    }
            }

        // scale + mask + softmax
#pragma unroll
        for (int i = 0; i < 2; ++i) {
            int rr0 = regid(wh_, ww_, rbase + i * 16 + qr);
            int rr1 = regid(wh_, ww_, rbase + i * 16 + qr + 8);
#pragma unroll
            for (int j = 0; j < 8; ++j) {
                s[i][j][0] *= scale; s[i][j][1] *= scale;
                s[i][j][2] *= scale; s[i][j][3] *= scale;
                if (shifted) {
                    if (creg[2 * j]     != rr0) s[i][j][0] += -1e9f;
                    if (creg[2 * j + 1] != rr0) s[i][j][1] += -1e9f;
                    if (creg[2 * j]     != rr1) s[i][j][2] += -1e9f;
                    if (creg[2 * j + 1] != rr1) s[i][j][3] += -1e9f;
                }
            }
            float m0 = -3.4e38f, m1 = -3.4e38f;
#pragma unroll
            for (int j = 0; j < 8; ++j) {
                m0 = fmaxf(m0, fmaxf(s[i][j][0], s[i][j][1]));
                m1 = fmaxf(m1, fmaxf(s[i][j][2], s[i][j][3]));
            }
            m0 = fmaxf(m0, __shfl_xor_sync(0xffffffffu, m0, 1));
            m0 = fmaxf(m0, __shfl_xor_sync(0xffffffffu, m0, 2));
            m1 = fmaxf(m1, __shfl_xor_sync(0xffffffffu, m1, 1));
            m1 = fmaxf(m1, __shfl_xor_sync(0xffffffffu, m1, 2));
            float s0 = 0.f, s1 = 0.f;
#pragma unroll
            for (int j = 0; j < 8; ++j) {
                s[i][j][0] = __expf(s[i][j][0] - m0); s0 += s[i][j][0];
                s[i][j][1] = __expf(s[i][j][1] - m0); s0 += s[i][j][1];
                s[i][j][2] = __expf(s[i][j][2] - m1); s1 += s[i][j][2];
                s[i][j][3] = __expf(s[i][j][3] - m1); s1 += s[i][j][3];
            }
            s0 += __shfl_xor_sync(0xffffffffu, s0, 1);
            s0 += __shfl_xor_sync(0xffffffffu, s0, 2);
            s1 += __shfl_xor_sync(0xffffffffu, s1, 1);
            s1 += __shfl_xor_sync(0xffffffffu, s1, 2);
            float i0 = 1.f / s0, i1 = 1.f / s1;
#pragma unroll
            for (int j = 0; j < 8; ++j) {
                s[i][j][0] *= i0; s[i][j][1] *= i0;
                s[i][j][2] *= i1; s[i][j][3] *= i1;
            }
        }

        // pack P to A-fragments (hi/lo)
        uint32_t ph[2][4][4], pl[2][4][4];
#pragma unroll
        for (int i = 0; i < 2; ++i)
#pragma unroll
            for (int kt = 0; kt < 4; ++kt) {
                const float* e = s[i][2 * kt];
                const float* o2 = s[i][2 * kt + 1];
                float h, h2;
                h = bf16rt(e[0]);  h2 = bf16rt(e[1]);
                ph[i][kt][0] = pk(h, h2);  pl[i][kt][0] = pk(e[0] - h, e[1] - h2);
                h = bf16rt(e[2]);  h2 = bf16rt(e[3]);
                ph[i][kt][1] = pk(h, h2);  pl[i][kt][1] = pk(e[2] - h, e[3] - h2);
                h = bf16rt(o2[0]); h2 = bf16rt(o2[1]);
                ph[i][kt][2] = pk(h, h2);  pl[i][kt][2] = pk(o2[0] - h, o2[1] - h2);
                h = bf16rt(o2[2]); h2 = bf16rt(o2[3]);
                ph[i][kt][3] = pk(h, h2);  pl[i][kt][3] = pk(o2[2] - h, o2[3] - h2);
            }

        // O = P V
        float o[2][4][4];
#pragma unroll
        for (int i = 0; i < 2; ++i)
#pragma unroll
            for (int nt = 0; nt < 4; ++nt)
#pragma unroll
                for (int q = 0; q < 4; ++q) o[i][nt][q] = 0.f;
#pragma unroll
        for (int kt = 0; kt < 4; ++kt)
#pragma unroll
            for (int ng = 0; ng < 2; ++ng) {
                uint32_t vh4[4], vl4[4];
                uint32_t va = (uint32_t)((kt * 16 + v_k) * LDQ + hcol + ng * 16 + v_n) * 2;
                ldsm4t(vh4, smb + AVH + va);
                ldsm4t(vl4, smb + AVL + va);
#pragma unroll
                for (int term = 0; term < 3; ++term)
#pragma unroll
                    for (int i = 0; i < 2; ++i) {
                        const uint32_t* aa = (term == 2) ? pl[i][kt] : ph[i][kt];
                        const uint32_t* vv = (term == 1) ? vl4 : vh4;
                        mma16816(o[i][2 * ng],     aa, vv[0], vv[1]);
                        mma16816(o[i][2 * ng + 1], aa, vv[2], vv[3]);
                    }
            }

        // store attn-out (split bf16) into dead Q smem: own cols, own rows
#pragma unroll
        for (int i = 0; i < 2; ++i) {
#pragma unroll
            for (int nt = 0; nt < 4; ++nt) {
                int col = hcol + nt * 8 + qc;
                int r0 = rbase + i * 16 + qr;
                float v0 = o[i][nt][0], v1 = o[i][nt][1];
                float h0 = bf16rt(v0), h1 = bf16rt(v1);
                uint32_t off0 = (uint32_t)(r0 * LDQ + col) * 2;
                *(uint32_t*)(sb + AQH + off0) = pk(h0, h1);
                *(uint32_t*)(sb + AQL + off0) = pk(v0 - h0, v1 - h1);
                float v2 = o[i][nt][2], v3 = o[i][nt][3];
                float h2 = bf16rt(v2), h3 = bf16rt(v3);
                uint32_t off1 = (uint32_t)((r0 + 8) * LDQ + col) * 2;
                *(uint32_t*)(sb + AQH + off1) = pk(h2, h3);
                *(uint32_t*)(sb + AQL + off1) = pk(v2 - h2, v3 - h3);
            }
        }
    }
    __syncthreads();   // attn-out complete; K/V smem dead

    // ======= O-projection: [64,256] = A @ W_o^T, A in smem (AQH/AQL) =======
    const int mbase = (wid & 1) * 32;
    const int nbase = (wid >> 1) * 64;
    const uint32_t aHi = smb + AQH + (uint32_t)((mbase + r8 + ((grp & 1) << 3)) * LDQ + ((grp & 2) ? 8 : 0)) * 2;
    const uint32_t aLo = aHi + (AQL - AQH);
    const uint32_t bBase = smb + OB + (uint32_t)((nbase + b_n) * 72 + b_k) * 2;

    float d[2][8][4];
#pragma unroll
    for (int mf = 0; mf < 2; ++mf)
#pragma unroll
        for (int nf = 0; nf < 8; ++nf)
#pragma unroll
            for (int q = 0; q < 4; ++q) d[mf][nf][q] = 0.f;

    for (int c = 0; c < 4; ++c) {
#pragma unroll
        for (int i = 0; i < 16; ++i) {
            int g = tid + i * 256;
            int half = g >> 11, j = g & 2047;
            int n = j >> 3, kq = j & 7;
            const __nv_bfloat16* W = half ? wol : woh;
            uint4 v = *(const uint4*)(W + (size_t)n * 256 + c * 64 + kq * 8);
            *(uint4*)(sb + OB + half * OB_HALF + n * LDB_B + kq * 16) = v;
        }
        __syncthreads();
#pragma unroll
        for (int kk8 = 0; kk8 < 4; ++kk8) {
            const int kg = c * 64 + kk8 * 16;
            uint32_t ah[2][4], al[2][4];
            ldsm4(ah[0], aHi + (uint32_t)kg * 2);
            ldsm4(ah[1], aHi + 16u * (LDQ * 2) + (uint32_t)kg * 2);
            ldsm4(al[0], aLo + (uint32_t)kg * 2);
            ldsm4(al[1], aLo + 16u * (LDQ * 2) + (uint32_t)kg * 2);
            uint32_t bh4[4][4], bl4[4][4];
            const uint32_t bb = bBase + (uint32_t)kk8 * 32;
#pragma unroll
            for (int np = 0; np < 4; ++np) {
                ldsm4(bh4[np], bb + (uint32_t)np * (16 * LDB_B));
                ldsm4(bl4[np], bb + OB_HALF + (uint32_t)np * (16 * LDB_B));
            }
#pragma unroll
            for (int term = 0; term < 3; ++term)
#pragma unroll
                for (int mf = 0; mf < 2; ++mf)
#pragma unroll
                    for (int nf = 0; nf < 8; ++nf) {
                        const int np = nf >> 1, hv = (nf & 1) * 2;
                        const uint32_t* aa = (term == 2) ? al[mf] : ah[mf];
                        const uint32_t* bv = (term == 1) ? bl4[np] : bh4[np];
                        mma16816(d[mf][nf], aa, bv[hv], bv[hv + 1]);
                    }
        }
        if (c < 3) __syncthreads();
    }

    if (!shifted) {
        // pass 1: stage split-bf16 y in dead B smem, then coalesced uint4 stores
        __syncthreads();       // all warps done reading OB
#pragma unroll
        for (int mf = 0; mf < 2; ++mf)
#pragma unroll
            for (int h8 = 0; h8 < 2; ++h8) {
                int row = mbase + mf * 16 + h8 * 8 + qr;
#pragma unroll
                for (int nf = 0; nf < 8; ++nf) {
                    int col = nbase + nf * 8 + qc;
                    float v0 = d[mf][nf][h8 * 2]     + bo[col];
                    float v1 = d[mf][nf][h8 * 2 + 1] + bo[col + 1];
                    float h0 = bf16rt(v0), h1 = bf16rt(v1);
                    uint32_t off = (uint32_t)(row * 256 + col) * 2;
                    *(uint32_t*)(sb + OB + off)         = pk(h0, h1);
                    *(uint32_t*)(sb + OB + 32768 + off) = pk(v0 - h0, v1 - h1);
                }
            }
        __syncthreads();
#pragma unroll
        for (int i = 0; i < 16; ++i) {
            int g = tid + i * 256;               // 0..4095
            int half = g >> 11, j = g & 2047;    // 64 rows x 32 uint4
            int row = j >> 5, u = j & 31;
            int tok = win * 64 + row;
            int m = tok >> 12, w = (tok >> 6) & 63, tt = tok & 63;
            int gh = (w >> 3) * 8 + (tt >> 3);
            int gw = (w & 7) * 8 + (tt & 7);
            size_t base = (size_t)((m * 64 + gh) * 64 + gw) * 256 + u * 8;
            __nv_bfloat16* dst = half ? yl_out : yh_out;
            *(uint4*)(dst + base) = *(const uint4*)(sb + OB + half * 32768 + row * 512 + u * 16);
        }
    } else {
        // pass 2: direct fp32 image scatter (+roll back), full-sector float2 quads
#pragma unroll
        for (int mf = 0; mf < 2; ++mf)
#pragma unroll
            for (int h8 = 0; h8 < 2; ++h8) {
                int row = mbase + mf * 16 + h8 * 8 + qr;
                int tok = win * 64 + row;
                int m = tok >> 12, w = (tok >> 6) & 63, tt = tok & 63;
                int gh = ((w >> 3) * 8 + (tt >> 3) + sh) & 63;
                int gw = ((w & 7) * 8 + (tt & 7) + sh) & 63;
                size_t base = (size_t)((m * 64 + gh) * 64 + gw) * 256;
#pragma unroll
                for (int nf = 0; nf < 8; ++nf) {
                    int col = nbase + nf * 8 + qc;
                    float v0 = d[mf][nf][h8 * 2]     + bo[col];
                    float v1 = d[mf][nf][h8 * 2 + 1] + bo[col + 1];
                    *(float2*)(f32_out + base + col) = make_float2(v0, v1);
                }
            }
    }
}

// ======================= launch =======================
extern "C" void kernel_launch(void* const* d_in, const int* in_sizes, int n_in,
                              void* d_out, int out_size) {
    (void)in_sizes; (void)n_in; (void)out_size;
    const float* x    = (const float*)d_in[0];
    const float* wqkv = (const float*)d_in[1];
    const float* bqkv = (const float*)d_in[2];
    const float* wo   = (const float*)d_in[3];
    const float* bo   = (const float*)d_in[4];
    float* out = (float*)d_out;

    cudaFuncSetAttribute(gemm_qkv,   cudaFuncAttributeMaxDynamicSharedMemorySize, GS_SMEM);
    cudaFuncSetAttribute(attn_fused, cudaFuncAttributeMaxDynamicSharedMemorySize, AT_SMEM);

    __nv_bfloat16 *wqh, *wql, *woh, *wol, *qh, *ql, *yh, *yl;
    cudaGetSymbolAddress((void**)&wqh, g_wtq_hi);
    cudaGetSymbolAddress((void**)&wql, g_wtq_lo);
    cudaGetSymbolAddress((void**)&woh, g_wto_hi);
    cudaGetSymbolAddress((void**)&wol, g_wto_lo);
    cudaGetSymbolAddress((void**)&qh,  g_qkvh);
    cudaGetSymbolAddress((void**)&ql,  g_qkvl);
    cudaGetSymbolAddress((void**)&yh,  g_yh);
    cudaGetSymbolAddress((void**)&yl,  g_yl);

    prep_kernel<<<1024, 256>>>(wqkv, wo);

    for (int pass = 0; pass < 2; ++pass) {
        gemm_qkv<<<1024, 256, GS_SMEM>>>(x, yh, yl, wqh, wql, bqkv, qh, ql, pass);
        attn_fused<<<2048, 256, AT_SMEM>>>(qh, ql, woh, wol, bo, yh, yl, out, pass);
    }
}

// round 12
// speedup vs baseline: 1.0733x; 1.0733x over previous
#include <cuda_runtime.h>
#include <cuda_bf16.h>
#include <cstdint>

// Swin layer: split-bf16 HMMA QKV GEMM + fused flash-attention + O-proj.
// R11: 512-thread CTAs (16 warps) for latency hiding; per-fragment attention
// streaming to stay under the 128-reg cap.
#define NTOK 131072          // 32 * 64 * 64 tokens

// -------- device scratch (allocation-free rule) --------
__device__ __nv_bfloat16 g_qkvh[(size_t)NTOK * 768];
__device__ __nv_bfloat16 g_qkvl[(size_t)NTOK * 768];
__device__ __nv_bfloat16 g_yh[NTOK * 256];      // pass-1 output, image layout
__device__ __nv_bfloat16 g_yl[NTOK * 256];
__device__ __nv_bfloat16 g_wtq_hi[768 * 256];   // W_qkv^T  [N][K]
__device__ __nv_bfloat16 g_wtq_lo[768 * 256];
__device__ __nv_bfloat16 g_wto_hi[256 * 256];   // W_o^T    [N][K]
__device__ __nv_bfloat16 g_wto_lo[256 * 256];

// ======================= helpers =======================
__device__ __forceinline__ uint32_t smem_u32(const void* p) {
    uint32_t a;
    asm("{ .reg .u64 t; cvta.to.shared.u64 t, %1; cvt.u32.u64 %0, t; }" : "=r"(a) : "l"(p));
    return a;
}
__device__ __forceinline__ void ldsm4(uint32_t r[4], uint32_t addr) {
    asm volatile("ldmatrix.sync.aligned.m8n8.x4.shared.b16 {%0,%1,%2,%3}, [%4];"
                 : "=r"(r[0]), "=r"(r[1]), "=r"(r[2]), "=r"(r[3]) : "r"(addr));
}
__device__ __forceinline__ void ldsm4t(uint32_t r[4], uint32_t addr) {
    asm volatile("ldmatrix.sync.aligned.m8n8.x4.trans.shared.b16 {%0,%1,%2,%3}, [%4];"
                 : "=r"(r[0]), "=r"(r[1]), "=r"(r[2]), "=r"(r[3]) : "r"(addr));
}
__device__ __forceinline__ void mma16816(float d[4], const uint32_t a[4],
                                         uint32_t b0, uint32_t b1) {
    asm volatile(
        "mma.sync.aligned.m16n8k16.row.col.f32.bf16.bf16.f32 "
        "{%0,%1,%2,%3}, {%4,%5,%6,%7}, {%8,%9}, {%0,%1,%2,%3};"
        : "+f"(d[0]), "+f"(d[1]), "+f"(d[2]), "+f"(d[3])
        : "r"(a[0]), "r"(a[1]), "r"(a[2]), "r"(a[3]), "r"(b0), "r"(b1));
}
__device__ __forceinline__ uint32_t pk(float c0, float c1) {   // bf16x2(lo=c0, hi=c1)
    uint32_t d;
    asm("cvt.rn.bf16x2.f32 %0, %1, %2;" : "=r"(d) : "f"(c1), "f"(c0));
    return d;
}
__device__ __forceinline__ float bf16rt(float v) {
    return __bfloat162float(__float2bfloat16(v));
}
__device__ __forceinline__ int regid(int wh, int ww, int t) {
    int r = t >> 3, c = t & 7;
    int hr = (wh == 7) ? ((r < 4) ? 1 : 2) : 0;
    int wr = (ww == 7) ? ((c < 4) ? 1 : 2) : 0;
    return hr * 3 + wr;
}

// ======================= prep: W^T hi/lo split =======================
__global__ void prep_kernel(const float* __restrict__ wqkv, const float* __restrict__ wo) {
    int i = blockIdx.x * blockDim.x + threadIdx.x;
    if (i < 768 * 256) {
        int n = i >> 8, k = i & 255;
        float f = wqkv[k * 768 + n];
        float h = bf16rt(f);
        g_wtq_hi[i] = __float2bfloat16(h);
        g_wtq_lo[i] = __float2bfloat16(f - h);
    } else if (i < 768 * 256 + 256 * 256) {
        int j = i - 768 * 256;
        int n = j >> 8, k = j & 255;
        float f = wo[k * 256 + n];
        float h = bf16rt(f);
        g_wto_hi[j] = __float2bfloat16(h);
        g_wto_lo[j] = __float2bfloat16(f - h);
    }
}

// ======================= QKV GEMM kernel (512 threads) =======================
#define LDA      264
#define A_LO_OFF 67584
#define GB_OFF   135168
#define B_BUF    36864
#define B_HALF   18432
#define LDB_B    144
#define GS_SMEM  (GB_OFF + 2 * B_BUF)

__global__ __launch_bounds__(512, 1)
void gemm_qkv(const float* __restrict__ xin,
              const __nv_bfloat16* __restrict__ yh_in, const __nv_bfloat16* __restrict__ yl_in,
              const __nv_bfloat16* __restrict__ wh, const __nv_bfloat16* __restrict__ wl,
              const float* __restrict__ bias,
              __nv_bfloat16* __restrict__ qh_out, __nv_bfloat16* __restrict__ ql_out,
              int shifted)
{
    extern __shared__ char sb[];
    const uint32_t smb = smem_u32(sb);
    const int tid = threadIdx.x, wid = tid >> 5, lane = tid & 31;
    const int blk = blockIdx.x;
    const int sh = shifted ? 4 : 0;

    // ---- load A (128 rows x 256), window-gather with roll ----
    for (int g = tid; g < 4096; g += 512) {
        int t = g >> 5;
        int col0 = (g & 31) * 8;
        int tok = blk * 128 + t;
        int m = tok >> 12, w = (tok >> 6) & 63, tt = tok & 63;
        int gh = ((w >> 3) * 8 + (tt >> 3) + sh) & 63;
        int gw = ((w & 7) * 8 + (tt & 7) + sh) & 63;
        size_t idx = (size_t)((m * 64 + gh) * 64 + gw) * 256 + col0;
        uint32_t off = ((uint32_t)t * LDA + col0) * 2;
        if (!shifted) {
            const float* sp = xin + idx;
            float4 f0 = *(const float4*)sp, f1 = *(const float4*)(sp + 4);
            float fv[8] = {f0.x, f0.y, f0.z, f0.w, f1.x, f1.y, f1.z, f1.w};
            uint32_t hw[4], lw[4];
#pragma unroll
            for (int q = 0; q < 4; ++q) {
                float h0 = bf16rt(fv[2 * q]), h1 = bf16rt(fv[2 * q + 1]);
                hw[q] = pk(h0, h1);
                lw[q] = pk(fv[2 * q] - h0, fv[2 * q + 1] - h1);
            }
            *(uint4*)(sb + off)            = make_uint4(hw[0], hw[1], hw[2], hw[3]);
            *(uint4*)(sb + A_LO_OFF + off) = make_uint4(lw[0], lw[1], lw[2], lw[3]);
        } else {
            *(uint4*)(sb + off)            = *(const uint4*)(yh_in + idx);
            *(uint4*)(sb + A_LO_OFF + off) = *(const uint4*)(yl_in + idx);
        }
    }

    // warp grid: 4m x 4n, warp tile 32 rows x 32 cols
    const int mbase = (wid & 3) * 32;
    const int nbase = (wid >> 2) * 32;
    const int grp = lane >> 3, r8 = lane & 7;
    const int a_row = mbase + r8 + ((grp & 1) << 3);
    const int a_kof = (grp & 2) ? 8 : 0;
    const uint32_t aHi = smb + (uint32_t)(a_row * LDA + a_kof) * 2;
    const uint32_t aLo = aHi + A_LO_OFF;
    const int b_n  = r8 + ((grp & 2) << 2);
    const int b_kof = (grp & 1) ? 8 : 0;
    const uint32_t bBase = smb + GB_OFF + (uint32_t)((nbase + b_n) * 72 + b_kof) * 2;
    const int qr = lane >> 2, qc = (lane & 3) * 2;

    for (int nt = 0; nt < 6; ++nt) {
        float d[2][4][4];
#pragma unroll
        for (int mf = 0; mf < 2; ++mf)
#pragma unroll
            for (int nf = 0; nf < 4; ++nf)
#pragma unroll
                for (int q = 0; q < 4; ++q) d[mf][nf][q] = 0.f;

#pragma unroll
        for (int i = 0; i < 4; ++i) {
            int g = tid + i * 512;
            int half = g >> 10, j = g & 1023;
            int n = j >> 3, kq = j & 7;
            const __nv_bfloat16* W = half ? wl : wh;
            uint4 v = *(const uint4*)(W + (size_t)(nt * 128 + n) * 256 + kq * 8);
            *(uint4*)(sb + GB_OFF + half * B_HALF + n * LDB_B + kq * 16) = v;
        }
        __syncthreads();

        for (int c = 0; c < 4; ++c) {
            uint4 stg[4];
            if (c < 3) {
#pragma unroll
                for (int i = 0; i < 4; ++i) {
                    int g = tid + i * 512;
                    int half = g >> 10, j = g & 1023;
                    int n = j >> 3, kq = j & 7;
                    const __nv_bfloat16* W = half ? wl : wh;
                    stg[i] = *(const uint4*)(W + (size_t)(nt * 128 + n) * 256 + (c + 1) * 64 + kq * 8);
                }
            }
            const uint32_t bb0 = bBase + (uint32_t)(c & 1) * B_BUF;
#pragma unroll
            for (int kk8 = 0; kk8 < 4; ++kk8) {
                const int kg = c * 64 + kk8 * 16;
                uint32_t ah[2][4], al[2][4];
                ldsm4(ah[0], aHi + (uint32_t)kg * 2);
                ldsm4(ah[1], aHi + 16u * (LDA * 2) + (uint32_t)kg * 2);
                ldsm4(al[0], aLo + (uint32_t)kg * 2);
                ldsm4(al[1], aLo + 16u * (LDA * 2) + (uint32_t)kg * 2);
                uint32_t bh[2][4], bl[2][4];
                const uint32_t bb = bb0 + (uint32_t)kk8 * 32;
#pragma unroll
                for (int np = 0; np < 2; ++np) {
                    ldsm4(bh[np], bb + (uint32_t)np * (16 * LDB_B));
                    ldsm4(bl[np], bb + B_HALF + (uint32_t)np * (16 * LDB_B));
                }
#pragma unroll
                for (int term = 0; term < 3; ++term)
#pragma unroll
                    for (int mf = 0; mf < 2; ++mf)
#pragma unroll
                        for (int nf = 0; nf < 4; ++nf) {
                            const int np = nf >> 1, hv = (nf & 1) * 2;
                            const uint32_t* aa = (term == 2) ? al[mf] : ah[mf];
                            const uint32_t* bv = (term == 1) ? bl[np] : bh[np];
                            mma16816(d[mf][nf], aa, bv[hv], bv[hv + 1]);
                        }
            }
            if (c < 3) {
#pragma unroll
                for (int i = 0; i < 4; ++i) {
                    int g = tid + i * 512;
                    int half = g >> 10, j = g & 1023;
                    int n = j >> 3, kq = j & 7;
                    *(uint4*)(sb + GB_OFF + ((c + 1) & 1) * B_BUF + half * B_HALF + n * LDB_B + kq * 16) = stg[i];
                }
            }
            __syncthreads();
        }

        // ---- epilogue: bias, stage in dead B smem, coalesced store ----
#pragma unroll
        for (int mf = 0; mf < 2; ++mf)
#pragma unroll
            for (int h8 = 0; h8 < 2; ++h8) {
                int row = mbase + mf * 16 + h8 * 8 + qr;
#pragma unroll
                for (int nf = 0; nf < 4; ++nf) {
                    int col = nbase + nf * 8 + qc;
                    float v0 = d[mf][nf][h8 * 2]     + bias[nt * 128 + col];
                    float v1 = d[mf][nf][h8 * 2 + 1] + bias[nt * 128 + col + 1];
                    float h0 = bf16rt(v0), h1 = bf16rt(v1);
                    uint32_t off = (uint32_t)(row * 128 + col) * 2;
                    *(uint32_t*)(sb + GB_OFF + off)         = pk(h0, h1);
                    *(uint32_t*)(sb + GB_OFF + 32768 + off) = pk(v0 - h0, v1 - h1);
                }
            }
        __syncthreads();
#pragma unroll
        for (int i = 0; i < 4; ++i) {
            int g = tid + i * 512;               // 0..2047
            int row = g >> 4, u = g & 15;        // 16 x uint4 per 128-col row
            size_t base = (size_t)(blk * 128 + row) * 768 + nt * 128 + u * 8;
            *(uint4*)(qh_out + base) = *(const uint4*)(sb + GB_OFF + row * 256 + u * 16);
            *(uint4*)(ql_out + base) = *(const uint4*)(sb + GB_OFF + 32768 + row * 256 + u * 16);
        }
        __syncthreads();
    }
}

// ======================= fused attention + O-proj kernel (512 threads) =======================
#define LDQ  264
#define AQH  0
#define AQL  33792
#define AKH  67584
#define AKL  101376
#define AVH  135168
#define AVL  168960
#define OB   67584            // O-proj B staging (overwrites K/V areas)
#define OB_HALF 36864
#define AT_SMEM 202752

__global__ __launch_bounds__(512, 1)
void attn_fused(const __nv_bfloat16* __restrict__ qkvh, const __nv_bfloat16* __restrict__ qkvl,
                const __nv_bfloat16* __restrict__ woh, const __nv_bfloat16* __restrict__ wol,
                const float* __restrict__ bo,
                __nv_bfloat16* __restrict__ yh_out, __nv_bfloat16* __restrict__ yl_out,
                float* __restrict__ f32_out, int shifted)
{
    extern __shared__ char sb[];
    const uint32_t smb = smem_u32(sb);
    const int tid = threadIdx.x, wid = tid >> 5, lane = tid & 31;
    const int win = blockIdx.x;
    const int wh_ = (win & 63) >> 3, ww_ = win & 7;
    const int sh = shifted ? 4 : 0;

    // ---- load pre-split qkv: straight uint4 copies (8 threads per row) ----
    {
        const int t = tid >> 3;
        const size_t rbase = (size_t)(win * 64 + t) * 768;
#pragma unroll
        for (int i = 0; i < 12; ++i) {
            int col0 = ((tid & 7) + i * 8) * 8;      // 0..760
            int sel = col0 >> 8, c = col0 & 255;
            uint32_t bh = (sel == 0) ? AQH : (sel == 1) ? AKH : AVH;
            uint32_t off = (uint32_t)(t * LDQ + c) * 2;
            *(uint4*)(sb + bh + off)         = *(const uint4*)(qkvh + rbase + col0);
            *(uint4*)(sb + bh + 33792 + off) = *(const uint4*)(qkvl + rbase + col0);
        }
    }
    __syncthreads();

    // warp task: head = wid>>1, 32-row half = wid&1
    const int head = wid >> 1;
    const int hcol = head * 32;
    const int rbase0 = (wid & 1) * 32;
    const int arow = lane & 15, acolh = (lane >> 4) * 8;
    const int grp = lane >> 3, r8 = lane & 7;
    const int b_n = r8 + ((grp & 2) << 2), b_k = (grp & 1) * 8;
    const int v_k = r8 + ((grp & 1) << 3), v_n = (grp & 2) << 2;
    const int qr = lane >> 2, qc = (lane & 3) * 2;
    const float scale = 0.17677669529663687f;

    int creg[16];
#pragma unroll
    for (int j = 0; j < 8; ++j) {
        creg[2 * j]     = regid(wh_, ww_, j * 8 + qc);
        creg[2 * j + 1] = regid(wh_, ww_, j * 8 + qc + 1);
    }

    // stream per 16-row fragment to bound live registers
#pragma unroll
    for (int fi = 0; fi < 2; ++fi) {
        const int rbase = rbase0 + fi * 16;
        uint32_t qhf[2][4], qlf[2][4];
#pragma unroll
        for (int kt = 0; kt < 2; ++kt) {
            uint32_t off = (uint32_t)((rbase + arow) * LDQ + hcol + kt * 16 + acolh) * 2;
            ldsm4(qhf[kt], smb + AQH + off);
            ldsm4(qlf[kt], smb + AQL + off);
        }

        float s[8][4];
#pragma unroll
        for (int j = 0; j < 8; ++j)
#pragma unroll
            for (int q = 0; q < 4; ++q) s[j][q] = 0.f;
#pragma unroll
        for (int kt = 0; kt < 2; ++kt)
#pragma unroll
            for (int ng = 0; ng < 4; ++ng) {
                uint32_t kh4[4], kl4[4];
                uint32_t ka = (uint32_t)((ng * 16 + b_n) * LDQ + hcol + kt * 16 + b_k) * 2;
                ldsm4(kh4, smb + AKH + ka);
                ldsm4(kl4, smb + AKL + ka);
#pragma unroll
                for (int term = 0; term < 3; ++term) {
                    const uint32_t* aa = (term == 2) ? qlf[kt] : qhf[kt];
                    const uint32_t* bv = (term == 1) ? kl4 : kh4;
                    mma16816(s[2 * ng],     aa, bv[0], bv[1]);
                    mma16816(s[2 * ng + 1], aa, bv[2], bv[3]);
                }
            }

        // scale + mask + softmax (rows rbase+qr and rbase+qr+8)
        {
            int rr0 = regid(wh_, ww_, rbase + qr);
            int rr1 = regid(wh_, ww_, rbase + qr + 8);
#pragma unroll
            for (int j = 0; j < 8; ++j) {
                s[j][0] *= scale; s[j][1] *= scale;
                s[j][2] *= scale; s[j][3] *= scale;
                if (shifted) {
                    if (creg[2 * j]     != rr0) s[j][0] += -1e9f;
                    if (creg[2 * j + 1] != rr0) s[j][1] += -1e9f;
                    if (creg[2 * j]     != rr1) s[j][2] += -1e9f;
                    if (creg[2 * j + 1] != rr1) s[j][3] += -1e9f;
                }
            }
            float m0 = -3.4e38f, m1 = -3.4e38f;
#pragma unroll
            for (int j = 0; j < 8; ++j) {
                m0 = fmaxf(m0, fmaxf(s[j][0], s[j][1]));
                m1 = fmaxf(m1, fmaxf(s[j][2], s[j][3]));
            }
            m0 = fmaxf(m0, __shfl_xor_sync(0xffffffffu, m0, 1));
            m0 = fmaxf(m0, __shfl_xor_sync(0xffffffffu, m0, 2));
            m1 = fmaxf(m1, __shfl_xor_sync(0xffffffffu, m1, 1));
            m1 = fmaxf(m1, __shfl_xor_sync(0xffffffffu, m1, 2));
            float s0 = 0.f, s1 = 0.f;
#pragma unroll
            for (int j = 0; j < 8; ++j) {
                s[j][0] = __expf(s[j][0] - m0); s0 += s[j][0];
                s[j][1] = __expf(s[j][1] - m0); s0 += s[j][1];
                s[j][2] = __expf(s[j][2] - m1); s1 += s[j][2];
                s[j][3] = __expf(s[j][3] - m1); s1 += s[j][3];
            }
            s0 += __shfl_xor_sync(0xffffffffu, s0, 1);
            s0 += __shfl_xor_sync(0xffffffffu, s0, 2);
            s1 += __shfl_xor_sync(0xffffffffu, s1, 1);
            s1 += __shfl_xor_sync(0xffffffffu, s1, 2);
            float i0 = 1.f / s0, i1 = 1.f / s1;
#pragma unroll
            for (int j = 0; j < 8; ++j) {
                s[j][0] *= i0; s[j][1] *= i0;
                s[j][2] *= i1; s[j][3] *= i1;
            }
        }

        // pack P to A-fragments (hi/lo)
        uint32_t ph[4][4], pl[4][4];
#pragma unroll
        for (int kt = 0; kt < 4; ++kt) {
            const float* e = s[2 * kt];
            const float* o2 = s[2 * kt + 1];
            float h, h2;
            h = bf16rt(e[0]);  h2 = bf16rt(e[1]);
            ph[kt][0] = pk(h, h2);  pl[kt][0] = pk(e[0] - h, e[1] - h2);
            h = bf16rt(e[2]);  h2 = bf16rt(e[3]);
            ph[kt][1] = pk(h, h2);  pl[kt][1] = pk(e[2] - h, e[3] - h2);
            h = bf16rt(o2[0]); h2 = bf16rt(o2[1]);
            ph[kt][2] = pk(h, h2);  pl[kt][2] = pk(o2[0] - h, o2[1] - h2);
            h = bf16rt(o2[2]); h2 = bf16rt(o2[3]);
            ph[kt][3] = pk(h, h2);  pl[kt][3] = pk(o2[2] - h, o2[3] - h2);
        }

        // O = P V
        float o[4][4];
#pragma unroll
        for (int nt = 0; nt < 4; ++nt)
#pragma unroll
            for (int q = 0; q < 4; ++q) o[nt][q] = 0.f;
#pragma unroll
        for (int kt = 0; kt < 4; ++kt)
#pragma unroll
            for (int ng = 0; ng < 2; ++ng) {
                uint32_t vh4[4], vl4[4];
                uint32_t va = (uint32_t)((kt * 16 + v_k) * LDQ + hcol + ng * 16 + v_n) * 2;
                ldsm4t(vh4, smb + AVH + va);
                ldsm4t(vl4, smb + AVL + va);
#pragma unroll
                for (int term = 0; term < 3; ++term) {
                    const uint32_t* aa = (term == 2) ? pl[kt] : ph[kt];
                    const uint32_t* vv = (term == 1) ? vl4 : vh4;
                    mma16816(o[2 * ng],     aa, vv[0], vv[1]);
                    mma16816(o[2 * ng + 1], aa, vv[2], vv[3]);
                }
            }

        // store attn-out (split bf16) into dead Q smem: own rows/cols
#pragma unroll
        for (int nt = 0; nt < 4; ++nt) {
            int col = hcol + nt * 8 + qc;
            int r0 = rbase + qr;
            float v0 = o[nt][0], v1 = o[nt][1];
            float h0 = bf16rt(v0), h1 = bf16rt(v1);
            uint32_t off0 = (uint32_t)(r0 * LDQ + col) * 2;
            *(uint32_t*)(sb + AQH + off0) = pk(h0, h1);
            *(uint32_t*)(sb + AQL + off0) = pk(v0 - h0, v1 - h1);
            float v2 = o[nt][2], v3 = o[nt][3];
            float h2 = bf16rt(v2), h3 = bf16rt(v3);
            uint32_t off1 = (uint32_t)((r0 + 8) * LDQ + col) * 2;
            *(uint32_t*)(sb + AQH + off1) = pk(h2, h3);
            *(uint32_t*)(sb + AQL + off1) = pk(v2 - h2, v3 - h3);
        }
    }
    __syncthreads();   // attn-out complete; K/V smem dead

    // ======= O-projection: [64,256] = A @ W_o^T; warp grid 2m x 8n =======
    const int mbase = (wid & 1) * 32;
    const int nbase = (wid >> 1) * 32;
    const uint32_t aHi = smb + AQH + (uint32_t)((mbase + r8 + ((grp & 1) << 3)) * LDQ + ((grp & 2) ? 8 : 0)) * 2;
    const uint32_t aLo = aHi + (AQL - AQH);
    const uint32_t bBase = smb + OB + (uint32_t)((nbase + b_n) * 72 + b_k) * 2;

    float d[2][4][4];
#pragma unroll
    for (int mf = 0; mf < 2; ++mf)
#pragma unroll
        for (int nf = 0; nf < 4; ++nf)
#pragma unroll
            for (int q = 0; q < 4; ++q) d[mf][nf][q] = 0.f;

    for (int c = 0; c < 4; ++c) {
#pragma unroll
        for (int i = 0; i < 8; ++i) {
            int g = tid + i * 512;
            int half = g >> 11, j = g & 2047;
            int n = j >> 3, kq = j & 7;
            const __nv_bfloat16* W = half ? wol : woh;
            uint4 v = *(const uint4*)(W + (size_t)n * 256 + c * 64 + kq * 8);
            *(uint4*)(sb + OB + half * OB_HALF + n * LDB_B + kq * 16) = v;
        }
        __syncthreads();
#pragma unroll
        for (int kk8 = 0; kk8 < 4; ++kk8) {
            const int kg = c * 64 + kk8 * 16;
            uint32_t ah[2][4], al[2][4];
            ldsm4(ah[0], aHi + (uint32_t)kg * 2);
            ldsm4(ah[1], aHi + 16u * (LDQ * 2) + (uint32_t)kg * 2);
            ldsm4(al[0], aLo + (uint32_t)kg * 2);
            ldsm4(al[1], aLo + 16u * (LDQ * 2) + (uint32_t)kg * 2);
            uint32_t bh4[2][4], bl4[2][4];
            const uint32_t bb = bBase + (uint32_t)kk8 * 32;
#pragma unroll
            for (int np = 0; np < 2; ++np) {
                ldsm4(bh4[np], bb + (uint32_t)np * (16 * LDB_B));
                ldsm4(bl4[np], bb + OB_HALF + (uint32_t)np * (16 * LDB_B));
            }
#pragma unroll
            for (int term = 0; term < 3; ++term)
#pragma unroll
                for (int mf = 0; mf < 2; ++mf)
#pragma unroll
                    for (int nf = 0; nf < 4; ++nf) {
                        const int np = nf >> 1, hv = (nf & 1) * 2;
                        const uint32_t* aa = (term == 2) ? al[mf] : ah[mf];
                        const uint32_t* bv = (term == 1) ? bl4[np] : bh4[np];
                        mma16816(d[mf][nf], aa, bv[hv], bv[hv + 1]);
                    }
        }
        if (c < 3) __syncthreads();
    }

    if (!shifted) {
        // pass 1: stage split-bf16 y in dead B smem, then coalesced uint4 stores
        __syncthreads();       // all warps done reading OB
#pragma unroll
        for (int mf = 0; mf < 2; ++mf)
#pragma unroll
            for (int h8 = 0; h8 < 2; ++h8) {
                int row = mbase + mf * 16 + h8 * 8 + qr;
#pragma unroll
                for (int nf = 0; nf < 4; ++nf) {
                    int col = nbase + nf * 8 + qc;
                    float v0 = d[mf][nf][h8 * 2]     + bo[col];
                    float v1 = d[mf][nf][h8 * 2 + 1] + bo[col + 1];
                    float h0 = bf16rt(v0), h1 = bf16rt(v1);
                    uint32_t off = (uint32_t)(row * 256 + col) * 2;
                    *(uint32_t*)(sb + OB + off)         = pk(h0, h1);
                    *(uint32_t*)(sb + OB + 32768 + off) = pk(v0 - h0, v1 - h1);
                }
            }
        __syncthreads();
#pragma unroll
        for (int i = 0; i < 8; ++i) {
            int g = tid + i * 512;               // 0..4095
            int half = g >> 11, j = g & 2047;    // 64 rows x 32 uint4
            int row = j >> 5, u = j & 31;
            int tok = win * 64 + row;
            int m = tok >> 12, w = (tok >> 6) & 63, tt = tok & 63;
            int gh = (w >> 3) * 8 + (tt >> 3);
            int gw = (w & 7) * 8 + (tt & 7);
            size_t base = (size_t)((m * 64 + gh) * 64 + gw) * 256 + u * 8;
            __nv_bfloat16* dst = half ? yl_out : yh_out;
            *(uint4*)(dst + base) = *(const uint4*)(sb + OB + half * 32768 + row * 512 + u * 16);
        }
    } else {
        // pass 2: direct fp32 image scatter (+roll back), full-sector float2 quads
#pragma unroll
        for (int mf = 0; mf < 2; ++mf)
#pragma unroll
            for (int h8 = 0; h8 < 2; ++h8) {
                int row = mbase + mf * 16 + h8 * 8 + qr;
                int tok = win * 64 + row;
                int m = tok >> 12, w = (tok >> 6) & 63, tt = tok & 63;
                int gh = ((w >> 3) * 8 + (tt >> 3) + sh) & 63;
                int gw = ((w & 7) * 8 + (tt & 7) + sh) & 63;
                size_t base = (size_t)((m * 64 + gh) * 64 + gw) * 256;
#pragma unroll
                for (int nf = 0; nf < 4; ++nf) {
                    int col = nbase + nf * 8 + qc;
                    float v0 = d[mf][nf][h8 * 2]     + bo[col];
                    float v1 = d[mf][nf][h8 * 2 + 1] + bo[col + 1];
                    *(float2*)(f32_out + base + col) = make_float2(v0, v1);
                }
            }
    }
}

// ======================= launch =======================
extern "C" void kernel_launch(void* const* d_in, const int* in_sizes, int n_in,
                              void* d_out, int out_size) {
    (void)in_sizes; (void)n_in; (void)out_size;
    const float* x    = (const float*)d_in[0];
    const float* wqkv = (const float*)d_in[1];
    const float* bqkv = (const float*)d_in[2];
    const float* wo   = (const float*)d_in[3];
    const float* bo   = (const float*)d_in[4];
    float* out = (float*)d_out;

    cudaFuncSetAttribute(gemm_qkv,   cudaFuncAttributeMaxDynamicSharedMemorySize, GS_SMEM);
    cudaFuncSetAttribute(attn_fused, cudaFuncAttributeMaxDynamicSharedMemorySize, AT_SMEM);

    __nv_bfloat16 *wqh, *wql, *woh, *wol, *qh, *ql, *yh, *yl;
    cudaGetSymbolAddress((void**)&wqh, g_wtq_hi);
    cudaGetSymbolAddress((void**)&wql, g_wtq_lo);
    cudaGetSymbolAddress((void**)&woh, g_wto_hi);
    cudaGetSymbolAddress((void**)&wol, g_wto_lo);
    cudaGetSymbolAddress((void**)&qh,  g_qkvh);
    cudaGetSymbolAddress((void**)&ql,  g_qkvl);
    cudaGetSymbolAddress((void**)&yh,  g_yh);
    cudaGetSymbolAddress((void**)&yl,  g_yl);

    prep_kernel<<<1024, 256>>>(wqkv, wo);

    for (int pass = 0; pass < 2; ++pass) {
        gemm_qkv<<<1024, 512, GS_SMEM>>>(x, yh, yl, wqh, wql, bqkv, qh, ql, pass);
        attn_fused<<<2048, 512, AT_SMEM>>>(qh, ql, woh, wol, bo, yh, yl, out, pass);
    }
}

// round 13
// speedup vs baseline: 1.2530x; 1.1674x over previous
#include <cuda_runtime.h>
#include <cuda_fp16.h>
#include <cstdint>

// Swin layer: split-fp16 HMMA GEMMs + fused flash-attention + O-proj.
// R13: fp16 everywhere; QKV GEMM uses 2-term split (A hi/lo x W single),
// attention + O-proj keep 3-term (near-exact). 33% fewer MMAs + half B
// traffic in the dominant kernel.
#define NTOK 131072          // 32 * 64 * 64 tokens

// -------- device scratch (allocation-free rule) --------
__device__ __half g_qkvh[(size_t)NTOK * 768];
__device__ __half g_qkvl[(size_t)NTOK * 768];
__device__ __half g_yh[NTOK * 256];      // pass-1 output, image layout
__device__ __half g_yl[NTOK * 256];
__device__ __half g_wtq_h[768 * 256];    // W_qkv^T [N][K], single fp16
__device__ __half g_wto_hi[256 * 256];   // W_o^T   [N][K], split
__device__ __half g_wto_lo[256 * 256];

// ======================= helpers =======================
__device__ __forceinline__ uint32_t smem_u32(const void* p) {
    uint32_t a;
    asm("{ .reg .u64 t; cvta.to.shared.u64 t, %1; cvt.u32.u64 %0, t; }" : "=r"(a) : "l"(p));
    return a;
}
__device__ __forceinline__ void ldsm4(uint32_t r[4], uint32_t addr) {
    asm volatile("ldmatrix.sync.aligned.m8n8.x4.shared.b16 {%0,%1,%2,%3}, [%4];"
                 : "=r"(r[0]), "=r"(r[1]), "=r"(r[2]), "=r"(r[3]) : "r"(addr));
}
__device__ __forceinline__ void ldsm4t(uint32_t r[4], uint32_t addr) {
    asm volatile("ldmatrix.sync.aligned.m8n8.x4.trans.shared.b16 {%0,%1,%2,%3}, [%4];"
                 : "=r"(r[0]), "=r"(r[1]), "=r"(r[2]), "=r"(r[3]) : "r"(addr));
}
__device__ __forceinline__ void mma16816(float d[4], const uint32_t a[4],
                                         uint32_t b0, uint32_t b1) {
    asm volatile(
        "mma.sync.aligned.m16n8k16.row.col.f32.f16.f16.f32 "
        "{%0,%1,%2,%3}, {%4,%5,%6,%7}, {%8,%9}, {%0,%1,%2,%3};"
        : "+f"(d[0]), "+f"(d[1]), "+f"(d[2]), "+f"(d[3])
        : "r"(a[0]), "r"(a[1]), "r"(a[2]), "r"(a[3]), "r"(b0), "r"(b1));
}
__device__ __forceinline__ uint32_t pk(float c0, float c1) {   // f16x2(lo=c0, hi=c1)
    uint32_t d;
    asm("cvt.rn.f16x2.f32 %0, %1, %2;" : "=r"(d) : "f"(c1), "f"(c0));
    return d;
}
__device__ __forceinline__ float f16rt(float v) {   // round-trip through fp16
    return __half2float(__float2half_rn(v));
}
__device__ __forceinline__ int regid(int wh, int ww, int t) {
    int r = t >> 3, c = t & 7;
    int hr = (wh == 7) ? ((r < 4) ? 1 : 2) : 0;
    int wr = (ww == 7) ? ((c < 4) ? 1 : 2) : 0;
    return hr * 3 + wr;
}

// ======================= prep: W^T fp16 (qkv single, wo split) =======================
__global__ void prep_kernel(const float* __restrict__ wqkv, const float* __restrict__ wo) {
    int i = blockIdx.x * blockDim.x + threadIdx.x;
    if (i < 768 * 256) {
        int n = i >> 8, k = i & 255;
        g_wtq_h[i] = __float2half_rn(wqkv[k * 768 + n]);
    } else if (i < 768 * 256 + 256 * 256) {
        int j = i - 768 * 256;
        int n = j >> 8, k = j & 255;
        float f = wo[k * 256 + n];
        float h = f16rt(f);
        g_wto_hi[j] = __float2half_rn(h);
        g_wto_lo[j] = __float2half_rn(f - h);
    }
}

// ======================= QKV GEMM kernel (512 threads, 2-term) =======================
#define LDA      264
#define A_LO_OFF 67584
#define GB_OFF   135168
#define B_BUF    18432               // one 128n x 64k fp16 chunk (stride 72)
#define LDB_B    144
#define GS_SMEM  (GB_OFF + 65536)    // B bufs (2x18432) OR epilogue staging (64KB)

__global__ __launch_bounds__(512, 1)
void gemm_qkv(const float* __restrict__ xin,
              const __half* __restrict__ yh_in, const __half* __restrict__ yl_in,
              const __half* __restrict__ wqh,
              const float* __restrict__ bias,
              __half* __restrict__ qh_out, __half* __restrict__ ql_out,
              int shifted)
{
    extern __shared__ char sb[];
    const uint32_t smb = smem_u32(sb);
    const int tid = threadIdx.x, wid = tid >> 5, lane = tid & 31;
    const int blk = blockIdx.x;
    const int sh = shifted ? 4 : 0;

    // ---- load A (128 rows x 256), window-gather with roll, fp16 hi/lo split ----
    for (int g = tid; g < 4096; g += 512) {
        int t = g >> 5;
        int col0 = (g & 31) * 8;
        int tok = blk * 128 + t;
        int m = tok >> 12, w = (tok >> 6) & 63, tt = tok & 63;
        int gh = ((w >> 3) * 8 + (tt >> 3) + sh) & 63;
        int gw = ((w & 7) * 8 + (tt & 7) + sh) & 63;
        size_t idx = (size_t)((m * 64 + gh) * 64 + gw) * 256 + col0;
        uint32_t off = ((uint32_t)t * LDA + col0) * 2;
        if (!shifted) {
            const float* sp = xin + idx;
            float4 f0 = *(const float4*)sp, f1 = *(const float4*)(sp + 4);
            float fv[8] = {f0.x, f0.y, f0.z, f0.w, f1.x, f1.y, f1.z, f1.w};
            uint32_t hw[4], lw[4];
#pragma unroll
            for (int q = 0; q < 4; ++q) {
                float h0 = f16rt(fv[2 * q]), h1 = f16rt(fv[2 * q + 1]);
                hw[q] = pk(h0, h1);
                lw[q] = pk(fv[2 * q] - h0, fv[2 * q + 1] - h1);
            }
            *(uint4*)(sb + off)            = make_uint4(hw[0], hw[1], hw[2], hw[3]);
            *(uint4*)(sb + A_LO_OFF + off) = make_uint4(lw[0], lw[1], lw[2], lw[3]);
        } else {
            *(uint4*)(sb + off)            = *(const uint4*)(yh_in + idx);
            *(uint4*)(sb + A_LO_OFF + off) = *(const uint4*)(yl_in + idx);
        }
    }

    // warp grid: 4m x 4n, warp tile 32 rows x 32 cols
    const int mbase = (wid & 3) * 32;
    const int nbase = (wid >> 2) * 32;
    const int grp = lane >> 3, r8 = lane & 7;
    const int a_row = mbase + r8 + ((grp & 1) << 3);
    const int a_kof = (grp & 2) ? 8 : 0;
    const uint32_t aHi = smb + (uint32_t)(a_row * LDA + a_kof) * 2;
    const uint32_t aLo = aHi + A_LO_OFF;
    const int b_n  = r8 + ((grp & 2) << 2);
    const int b_kof = (grp & 1) ? 8 : 0;
    const uint32_t bBase = smb + GB_OFF + (uint32_t)((nbase + b_n) * 72 + b_kof) * 2;
    const int qr = lane >> 2, qc = (lane & 3) * 2;

    for (int nt = 0; nt < 6; ++nt) {
        float d[2][4][4];
#pragma unroll
        for (int mf = 0; mf < 2; ++mf)
#pragma unroll
            for (int nf = 0; nf < 4; ++nf)
#pragma unroll
                for (int q = 0; q < 4; ++q) d[mf][nf][q] = 0.f;

        // stage B chunk 0 (single fp16, 16KB -> 1024 uint4 tasks)
#pragma unroll
        for (int i = 0; i < 2; ++i) {
            int g = tid + i * 512;
            int n = g >> 3, kq = g & 7;
            uint4 v = *(const uint4*)(wqh + (size_t)(nt * 128 + n) * 256 + kq * 8);
            *(uint4*)(sb + GB_OFF + n * LDB_B + kq * 16) = v;
        }
        __syncthreads();

        for (int c = 0; c < 4; ++c) {
            uint4 stg[2];
            if (c < 3) {
#pragma unroll
                for (int i = 0; i < 2; ++i) {
                    int g = tid + i * 512;
                    int n = g >> 3, kq = g & 7;
                    stg[i] = *(const uint4*)(wqh + (size_t)(nt * 128 + n) * 256 + (c + 1) * 64 + kq * 8);
                }
            }
            const uint32_t bb0 = bBase + (uint32_t)(c & 1) * B_BUF;
#pragma unroll
            for (int kk8 = 0; kk8 < 4; ++kk8) {
                const int kg = c * 64 + kk8 * 16;
                uint32_t ah[2][4], al[2][4];
                ldsm4(ah[0], aHi + (uint32_t)kg * 2);
                ldsm4(ah[1], aHi + 16u * (LDA * 2) + (uint32_t)kg * 2);
                ldsm4(al[0], aLo + (uint32_t)kg * 2);
                ldsm4(al[1], aLo + 16u * (LDA * 2) + (uint32_t)kg * 2);
                uint32_t bh[2][4];
                const uint32_t bb = bb0 + (uint32_t)kk8 * 32;
#pragma unroll
                for (int np = 0; np < 2; ++np)
                    ldsm4(bh[np], bb + (uint32_t)np * (16 * LDB_B));
                // 2-term: (ah + al) x Wh
#pragma unroll
                for (int term = 0; term < 2; ++term)
#pragma unroll
                    for (int mf = 0; mf < 2; ++mf)
#pragma unroll
                        for (int nf = 0; nf < 4; ++nf) {
                            const int np = nf >> 1, hv = (nf & 1) * 2;
                            const uint32_t* aa = term ? al[mf] : ah[mf];
                            mma16816(d[mf][nf], aa, bh[np][hv], bh[np][hv + 1]);
                        }
            }
            if (c < 3) {
#pragma unroll
                for (int i = 0; i < 2; ++i) {
                    int g = tid + i * 512;
                    int n = g >> 3, kq = g & 7;
                    *(uint4*)(sb + GB_OFF + ((c + 1) & 1) * B_BUF + n * LDB_B + kq * 16) = stg[i];
                }
            }
            __syncthreads();
        }

        // ---- epilogue: bias, stage in dead B smem, coalesced store ----
#pragma unroll
        for (int mf = 0; mf < 2; ++mf)
#pragma unroll
            for (int h8 = 0; h8 < 2; ++h8) {
                int row = mbase + mf * 16 + h8 * 8 + qr;
#pragma unroll
                for (int nf = 0; nf < 4; ++nf) {
                    int col = nbase + nf * 8 + qc;
                    float v0 = d[mf][nf][h8 * 2]     + bias[nt * 128 + col];
                    float v1 = d[mf][nf][h8 * 2 + 1] + bias[nt * 128 + col + 1];
                    float h0 = f16rt(v0), h1 = f16rt(v1);
                    uint32_t off = (uint32_t)(row * 128 + col) * 2;
                    *(uint32_t*)(sb + GB_OFF + off)         = pk(h0, h1);
                    *(uint32_t*)(sb + GB_OFF + 32768 + off) = pk(v0 - h0, v1 - h1);
                }
            }
        __syncthreads();
#pragma unroll
        for (int i = 0; i < 4; ++i) {
            int g = tid + i * 512;               // 0..2047
            int row = g >> 4, u = g & 15;        // 16 x uint4 per 128-col row
            size_t base = (size_t)(blk * 128 + row) * 768 + nt * 128 + u * 8;
            *(uint4*)(qh_out + base) = *(const uint4*)(sb + GB_OFF + row * 256 + u * 16);
            *(uint4*)(ql_out + base) = *(const uint4*)(sb + GB_OFF + 32768 + row * 256 + u * 16);
        }
        __syncthreads();
    }
}

// ======================= fused attention + O-proj kernel (512 threads) =======================
#define LDQ  264
#define AQH  0
#define AQL  33792
#define AKH  67584
#define AKL  101376
#define AVH  135168
#define AVL  168960
#define OB   67584            // O-proj B staging (overwrites K/V areas)
#define OB_HALF 36864
#define AT_SMEM 202752

__global__ __launch_bounds__(512, 1)
void attn_fused(const __half* __restrict__ qkvh, const __half* __restrict__ qkvl,
                const __half* __restrict__ woh, const __half* __restrict__ wol,
                const float* __restrict__ bo,
                __half* __restrict__ yh_out, __half* __restrict__ yl_out,
                float* __restrict__ f32_out, int shifted)
{
    extern __shared__ char sb[];
    const uint32_t smb = smem_u32(sb);
    const int tid = threadIdx.x, wid = tid >> 5, lane = tid & 31;
    const int win = blockIdx.x;
    const int wh_ = (win & 63) >> 3, ww_ = win & 7;
    const int sh = shifted ? 4 : 0;

    // ---- load pre-split qkv: straight uint4 copies (8 threads per row) ----
    {
        const int t = tid >> 3;
        const size_t rbase = (size_t)(win * 64 + t) * 768;
#pragma unroll
        for (int i = 0; i < 12; ++i) {
            int col0 = ((tid & 7) + i * 8) * 8;      // 0..760
            int sel = col0 >> 8, c = col0 & 255;
            uint32_t bh = (sel == 0) ? AQH : (sel == 1) ? AKH : AVH;
            uint32_t off = (uint32_t)(t * LDQ + c) * 2;
            *(uint4*)(sb + bh + off)         = *(const uint4*)(qkvh + rbase + col0);
            *(uint4*)(sb + bh + 33792 + off) = *(const uint4*)(qkvl + rbase + col0);
        }
    }
    __syncthreads();

    // warp task: head = wid>>1, 32-row half = wid&1
    const int head = wid >> 1;
    const int hcol = head * 32;
    const int rbase0 = (wid & 1) * 32;
    const int arow = lane & 15, acolh = (lane >> 4) * 8;
    const int grp = lane >> 3, r8 = lane & 7;
    const int b_n = r8 + ((grp & 2) << 2), b_k = (grp & 1) * 8;
    const int v_k = r8 + ((grp & 1) << 3), v_n = (grp & 2) << 2;
    const int qr = lane >> 2, qc = (lane & 3) * 2;
    const float scale = 0.17677669529663687f;

    int creg[16];
#pragma unroll
    for (int j = 0; j < 8; ++j) {
        creg[2 * j]     = regid(wh_, ww_, j * 8 + qc);
        creg[2 * j + 1] = regid(wh_, ww_, j * 8 + qc + 1);
    }

    // stream per 16-row fragment to bound live registers
#pragma unroll
    for (int fi = 0; fi < 2; ++fi) {
        const int rbase = rbase0 + fi * 16;
        uint32_t qhf[2][4], qlf[2][4];
#pragma unroll
        for (int kt = 0; kt < 2; ++kt) {
            uint32_t off = (uint32_t)((rbase + arow) * LDQ + hcol + kt * 16 + acolh) * 2;
            ldsm4(qhf[kt], smb + AQH + off);
            ldsm4(qlf[kt], smb + AQL + off);
        }

        float s[8][4];
#pragma unroll
        for (int j = 0; j < 8; ++j)
#pragma unroll
            for (int q = 0; q < 4; ++q) s[j][q] = 0.f;
#pragma unroll
        for (int kt = 0; kt < 2; ++kt)
#pragma unroll
            for (int ng = 0; ng < 4; ++ng) {
                uint32_t kh4[4], kl4[4];
                uint32_t ka = (uint32_t)((ng * 16 + b_n) * LDQ + hcol + kt * 16 + b_k) * 2;
                ldsm4(kh4, smb + AKH + ka);
                ldsm4(kl4, smb + AKL + ka);
#pragma unroll
                for (int term = 0; term < 3; ++term) {
                    const uint32_t* aa = (term == 2) ? qlf[kt] : qhf[kt];
                    const uint32_t* bv = (term == 1) ? kl4 : kh4;
                    mma16816(s[2 * ng],     aa, bv[0], bv[1]);
                    mma16816(s[2 * ng + 1], aa, bv[2], bv[3]);
                }
            }

        // scale + mask + softmax (rows rbase+qr and rbase+qr+8)
        {
            int rr0 = regid(wh_, ww_, rbase + qr);
            int rr1 = regid(wh_, ww_, rbase + qr + 8);
#pragma unroll
            for (int j = 0; j < 8; ++j) {
                s[j][0] *= scale; s[j][1] *= scale;
                s[j][2] *= scale; s[j][3] *= scale;
                if (shifted) {
                    if (creg[2 * j]     != rr0) s[j][0] += -1e9f;
                    if (creg[2 * j + 1] != rr0) s[j][1] += -1e9f;
                    if (creg[2 * j]     != rr1) s[j][2] += -1e9f;
                    if (creg[2 * j + 1] != rr1) s[j][3] += -1e9f;
                }
            }
            float m0 = -3.4e38f, m1 = -3.4e38f;
#pragma unroll
            for (int j = 0; j < 8; ++j) {
                m0 = fmaxf(m0, fmaxf(s[j][0], s[j][1]));
                m1 = fmaxf(m1, fmaxf(s[j][2], s[j][3]));
            }
            m0 = fmaxf(m0, __shfl_xor_sync(0xffffffffu, m0, 1));
            m0 = fmaxf(m0, __shfl_xor_sync(0xffffffffu, m0, 2));
            m1 = fmaxf(m1, __shfl_xor_sync(0xffffffffu, m1, 1));
            m1 = fmaxf(m1, __shfl_xor_sync(0xffffffffu, m1, 2));
            float s0 = 0.f, s1 = 0.f;
#pragma unroll
            for (int j = 0; j < 8; ++j) {
                s[j][0] = __expf(s[j][0] - m0); s0 += s[j][0];
                s[j][1] = __expf(s[j][1] - m0); s0 += s[j][1];
                s[j][2] = __expf(s[j][2] - m1); s1 += s[j][2];
                s[j][3] = __expf(s[j][3] - m1); s1 += s[j][3];
            }
            s0 += __shfl_xor_sync(0xffffffffu, s0, 1);
            s0 += __shfl_xor_sync(0xffffffffu, s0, 2);
            s1 += __shfl_xor_sync(0xffffffffu, s1, 1);
            s1 += __shfl_xor_sync(0xffffffffu, s1, 2);
            float i0 = 1.f / s0, i1 = 1.f / s1;
#pragma unroll
            for (int j = 0; j < 8; ++j) {
                s[j][0] *= i0; s[j][1] *= i0;
                s[j][2] *= i1; s[j][3] *= i1;
            }
        }

        // pack P to A-fragments (hi/lo)
        uint32_t ph[4][4], pl[4][4];
#pragma unroll
        for (int kt = 0; kt < 4; ++kt) {
            const float* e = s[2 * kt];
            const float* o2 = s[2 * kt + 1];
            float h, h2;
            h = f16rt(e[0]);  h2 = f16rt(e[1]);
            ph[kt][0] = pk(h, h2);  pl[kt][0] = pk(e[0] - h, e[1] - h2);
            h = f16rt(e[2]);  h2 = f16rt(e[3]);
            ph[kt][1] = pk(h, h2);  pl[kt][1] = pk(e[2] - h, e[3] - h2);
            h = f16rt(o2[0]); h2 = f16rt(o2[1]);
            ph[kt][2] = pk(h, h2);  pl[kt][2] = pk(o2[0] - h, o2[1] - h2);
            h = f16rt(o2[2]); h2 = f16rt(o2[3]);
            ph[kt][3] = pk(h, h2);  pl[kt][3] = pk(o2[2] - h, o2[3] - h2);
        }

        // O = P V
        float o[4][4];
#pragma unroll
        for (int nt = 0; nt < 4; ++nt)
#pragma unroll
            for (int q = 0; q < 4; ++q) o[nt][q] = 0.f;
#pragma unroll
        for (int kt = 0; kt < 4; ++kt)
#pragma unroll
            for (int ng = 0; ng < 2; ++ng) {
                uint32_t vh4[4], vl4[4];
                uint32_t va = (uint32_t)((kt * 16 + v_k) * LDQ + hcol + ng * 16 + v_n) * 2;
                ldsm4t(vh4, smb + AVH + va);
                ldsm4t(vl4, smb + AVL + va);
#pragma unroll
                for (int term = 0; term < 3; ++term) {
                    const uint32_t* aa = (term == 2) ? pl[kt] : ph[kt];
                    const uint32_t* vv = (term == 1) ? vl4 : vh4;
                    mma16816(o[2 * ng],     aa, vv[0], vv[1]);
                    mma16816(o[2 * ng + 1], aa, vv[2], vv[3]);
                }
            }

        // store attn-out (split fp16) into dead Q smem: own rows/cols
#pragma unroll
        for (int nt = 0; nt < 4; ++nt) {
            int col = hcol + nt * 8 + qc;
            int r0 = rbase + qr;
            float v0 = o[nt][0], v1 = o[nt][1];
            float h0 = f16rt(v0), h1 = f16rt(v1);
            uint32_t off0 = (uint32_t)(r0 * LDQ + col) * 2;
            *(uint32_t*)(sb + AQH + off0) = pk(h0, h1);
            *(uint32_t*)(sb + AQL + off0) = pk(v0 - h0, v1 - h1);
            float v2 = o[nt][2], v3 = o[nt][3];
            float h2 = f16rt(v2), h3 = f16rt(v3);
            uint32_t off1 = (uint32_t)((r0 + 8) * LDQ + col) * 2;
            *(uint32_t*)(sb + AQH + off1) = pk(h2, h3);
            *(uint32_t*)(sb + AQL + off1) = pk(v2 - h2, v3 - h3);
        }
    }
    __syncthreads();   // attn-out complete; K/V smem dead

    // ======= O-projection: [64,256] = A @ W_o^T; warp grid 2m x 8n, 3-term =======
    const int mbase = (wid & 1) * 32;
    const int nbase = (wid >> 1) * 32;
    const uint32_t aHi = smb + AQH + (uint32_t)((mbase + r8 + ((grp & 1) << 3)) * LDQ + ((grp & 2) ? 8 : 0)) * 2;
    const uint32_t aLo = aHi + (AQL - AQH);
    const uint32_t bBase = smb + OB + (uint32_t)((nbase + b_n) * 72 + b_k) * 2;

    float d[2][4][4];
#pragma unroll
    for (int mf = 0; mf < 2; ++mf)
#pragma unroll
        for (int nf = 0; nf < 4; ++nf)
#pragma unroll
            for (int q = 0; q < 4; ++q) d[mf][nf][q] = 0.f;

    for (int c = 0; c < 4; ++c) {
#pragma unroll
        for (int i = 0; i < 8; ++i) {
            int g = tid + i * 512;
            int half_ = g >> 11, j = g & 2047;
            int n = j >> 3, kq = j & 7;
            const __half* W = half_ ? wol : woh;
            uint4 v = *(const uint4*)(W + (size_t)n * 256 + c * 64 + kq * 8);
            *(uint4*)(sb + OB + half_ * OB_HALF + n * LDB_B + kq * 16) = v;
        }
        __syncthreads();
#pragma unroll
        for (int kk8 = 0; kk8 < 4; ++kk8) {
            const int kg = c * 64 + kk8 * 16;
            uint32_t ah[2][4], al[2][4];
            ldsm4(ah[0], aHi + (uint32_t)kg * 2);
            ldsm4(ah[1], aHi + 16u * (LDQ * 2) + (uint32_t)kg * 2);
            ldsm4(al[0], aLo + (uint32_t)kg * 2);
            ldsm4(al[1], aLo + 16u * (LDQ * 2) + (uint32_t)kg * 2);
            uint32_t bh4[2][4], bl4[2][4];
            const uint32_t bb = bBase + (uint32_t)kk8 * 32;
#pragma unroll
            for (int np = 0; np < 2; ++np) {
                ldsm4(bh4[np], bb + (uint32_t)np * (16 * LDB_B));
                ldsm4(bl4[np], bb + OB_HALF + (uint32_t)np * (16 * LDB_B));
            }
#pragma unroll
            for (int term = 0; term < 3; ++term)
#pragma unroll
                for (int mf = 0; mf < 2; ++mf)
#pragma unroll
                    for (int nf = 0; nf < 4; ++nf) {
                        const int np = nf >> 1, hv = (nf & 1) * 2;
                        const uint32_t* aa = (term == 2) ? al[mf] : ah[mf];
                        const uint32_t* bv = (term == 1) ? bl4[np] : bh4[np];
                        mma16816(d[mf][nf], aa, bv[hv], bv[hv + 1]);
                    }
        }
        if (c < 3) __syncthreads();
    }

    if (!shifted) {
        // pass 1: stage split-fp16 y in dead B smem, then coalesced uint4 stores
        __syncthreads();       // all warps done reading OB
#pragma unroll
        for (int mf = 0; mf < 2; ++mf)
#pragma unroll
            for (int h8 = 0; h8 < 2; ++h8) {
                int row = mbase + mf * 16 + h8 * 8 + qr;
#pragma unroll
                for (int nf = 0; nf < 4; ++nf) {
                    int col = nbase + nf * 8 + qc;
                    float v0 = d[mf][nf][h8 * 2]     + bo[col];
                    float v1 = d[mf][nf][h8 * 2 + 1] + bo[col + 1];
                    float h0 = f16rt(v0), h1 = f16rt(v1);
                    uint32_t off = (uint32_t)(row * 256 + col) * 2;
                    *(uint32_t*)(sb + OB + off)         = pk(h0, h1);
                    *(uint32_t*)(sb + OB + 32768 + off) = pk(v0 - h0, v1 - h1);
                }
            }
        __syncthreads();
#pragma unroll
        for (int i = 0; i < 8; ++i) {
            int g = tid + i * 512;               // 0..4095
            int half_ = g >> 11, j = g & 2047;   // 64 rows x 32 uint4
            int row = j >> 5, u = j & 31;
            int tok = win * 64 + row;
            int m = tok >> 12, w = (tok >> 6) & 63, tt = tok & 63;
            int gh = (w >> 3) * 8 + (tt >> 3);
            int gw = (w & 7) * 8 + (tt & 7);
            size_t base = (size_t)((m * 64 + gh) * 64 + gw) * 256 + u * 8;
            __half* dst = half_ ? yl_out : yh_out;
            *(uint4*)(dst + base) = *(const uint4*)(sb + OB + half_ * 32768 + row * 512 + u * 16);
        }
    } else {
        // pass 2: direct fp32 image scatter (+roll back), full-sector float2 quads
#pragma unroll
        for (int mf = 0; mf < 2; ++mf)
#pragma unroll
            for (int h8 = 0; h8 < 2; ++h8) {
                int row = mbase + mf * 16 + h8 * 8 + qr;
                int tok = win * 64 + row;
                int m = tok >> 12, w = (tok >> 6) & 63, tt = tok & 63;
                int gh = ((w >> 3) * 8 + (tt >> 3) + sh) & 63;
                int gw = ((w & 7) * 8 + (tt & 7) + sh) & 63;
                size_t base = (size_t)((m * 64 + gh) * 64 + gw) * 256;
#pragma unroll
                for (int nf = 0; nf < 4; ++nf) {
                    int col = nbase + nf * 8 + qc;
                    float v0 = d[mf][nf][h8 * 2]     + bo[col];
                    float v1 = d[mf][nf][h8 * 2 + 1] + bo[col + 1];
                    *(float2*)(f32_out + base + col) = make_float2(v0, v1);
                }
            }
    }
}

// ======================= launch =======================
extern "C" void kernel_launch(void* const* d_in, const int* in_sizes, int n_in,
                              void* d_out, int out_size) {
    (void)in_sizes; (void)n_in; (void)out_size;
    const float* x    = (const float*)d_in[0];
    const float* wqkv = (const float*)d_in[1];
    const float* bqkv = (const float*)d_in[2];
    const float* wo   = (const float*)d_in[3];
    const float* bo   = (const float*)d_in[4];
    float* out = (float*)d_out;

    cudaFuncSetAttribute(gemm_qkv,   cudaFuncAttributeMaxDynamicSharedMemorySize, GS_SMEM);
    cudaFuncSetAttribute(attn_fused, cudaFuncAttributeMaxDynamicSharedMemorySize, AT_SMEM);

    __half *wqh, *woh, *wol, *qh, *ql, *yh, *yl;
    cudaGetSymbolAddress((void**)&wqh, g_wtq_h);
    cudaGetSymbolAddress((void**)&woh, g_wto_hi);
    cudaGetSymbolAddress((void**)&wol, g_wto_lo);
    cudaGetSymbolAddress((void**)&qh,  g_qkvh);
    cudaGetSymbolAddress((void**)&ql,  g_qkvl);
    cudaGetSymbolAddress((void**)&yh,  g_yh);
    cudaGetSymbolAddress((void**)&yl,  g_yl);

    prep_kernel<<<1024, 256>>>(wqkv, wo);

    for (int pass = 0; pass < 2; ++pass) {
        gemm_qkv<<<1024, 512, GS_SMEM>>>(x, yh, yl, wqh, bqkv, qh, ql, pass);
        attn_fused<<<2048, 512, AT_SMEM>>>(qh, ql, woh, wol, bo, yh, yl, out, pass);
    }
}

// round 14
// speedup vs baseline: 1.3295x; 1.0611x over previous
#include <cuda_runtime.h>
#include <cuda_fp16.h>
#include <cstdint>

// Swin layer: split-fp16 HMMA GEMMs + fused flash-attention + O-proj.
// R14: O-proj also 2-term (attn-out split x single-fp16 W_o) — 22% fewer
// attn MMAs, half O-proj staging. Predicted rel_err ~4e-4 (gate 1e-3).
#define NTOK 131072          // 32 * 64 * 64 tokens

// -------- device scratch (allocation-free rule) --------
__device__ __half g_qkvh[(size_t)NTOK * 768];
__device__ __half g_qkvl[(size_t)NTOK * 768];
__device__ __half g_yh[NTOK * 256];      // pass-1 output, image layout
__device__ __half g_yl[NTOK * 256];
__device__ __half g_wtq_h[768 * 256];    // W_qkv^T [N][K], single fp16
__device__ __half g_wto_h[256 * 256];    // W_o^T   [N][K], single fp16

// ======================= helpers =======================
__device__ __forceinline__ uint32_t smem_u32(const void* p) {
    uint32_t a;
    asm("{ .reg .u64 t; cvta.to.shared.u64 t, %1; cvt.u32.u64 %0, t; }" : "=r"(a) : "l"(p));
    return a;
}
__device__ __forceinline__ void ldsm4(uint32_t r[4], uint32_t addr) {
    asm volatile("ldmatrix.sync.aligned.m8n8.x4.shared.b16 {%0,%1,%2,%3}, [%4];"
                 : "=r"(r[0]), "=r"(r[1]), "=r"(r[2]), "=r"(r[3]) : "r"(addr));
}
__device__ __forceinline__ void ldsm4t(uint32_t r[4], uint32_t addr) {
    asm volatile("ldmatrix.sync.aligned.m8n8.x4.trans.shared.b16 {%0,%1,%2,%3}, [%4];"
                 : "=r"(r[0]), "=r"(r[1]), "=r"(r[2]), "=r"(r[3]) : "r"(addr));
}
__device__ __forceinline__ void mma16816(float d[4], const uint32_t a[4],
                                         uint32_t b0, uint32_t b1) {
    asm volatile(
        "mma.sync.aligned.m16n8k16.row.col.f32.f16.f16.f32 "
        "{%0,%1,%2,%3}, {%4,%5,%6,%7}, {%8,%9}, {%0,%1,%2,%3};"
        : "+f"(d[0]), "+f"(d[1]), "+f"(d[2]), "+f"(d[3])
        : "r"(a[0]), "r"(a[1]), "r"(a[2]), "r"(a[3]), "r"(b0), "r"(b1));
}
__device__ __forceinline__ uint32_t pk(float c0, float c1) {   // f16x2(lo=c0, hi=c1)
    uint32_t d;
    asm("cvt.rn.f16x2.f32 %0, %1, %2;" : "=r"(d) : "f"(c1), "f"(c0));
    return d;
}
__device__ __forceinline__ float f16rt(float v) {   // round-trip through fp16
    return __half2float(__float2half_rn(v));
}
__device__ __forceinline__ int regid(int wh, int ww, int t) {
    int r = t >> 3, c = t & 7;
    int hr = (wh == 7) ? ((r < 4) ? 1 : 2) : 0;
    int wr = (ww == 7) ? ((c < 4) ? 1 : 2) : 0;
    return hr * 3 + wr;
}

// ======================= prep: W^T fp16 singles =======================
__global__ void prep_kernel(const float* __restrict__ wqkv, const float* __restrict__ wo) {
    int i = blockIdx.x * blockDim.x + threadIdx.x;
    if (i < 768 * 256) {
        int n = i >> 8, k = i & 255;
        g_wtq_h[i] = __float2half_rn(wqkv[k * 768 + n]);
    } else if (i < 768 * 256 + 256 * 256) {
        int j = i - 768 * 256;
        int n = j >> 8, k = j & 255;
        g_wto_h[j] = __float2half_rn(wo[k * 256 + n]);
    }
}

// ======================= QKV GEMM kernel (512 threads, 2-term) =======================
#define LDA      264
#define A_LO_OFF 67584
#define GB_OFF   135168
#define B_BUF    18432               // one 128n x 64k fp16 chunk (stride 72)
#define LDB_B    144
#define GS_SMEM  (GB_OFF + 65536)    // B bufs (2x18432) OR epilogue staging (64KB)

__global__ __launch_bounds__(512, 1)
void gemm_qkv(const float* __restrict__ xin,
              const __half* __restrict__ yh_in, const __half* __restrict__ yl_in,
              const __half* __restrict__ wqh,
              const float* __restrict__ bias,
              __half* __restrict__ qh_out, __half* __restrict__ ql_out,
              int shifted)
{
    extern __shared__ char sb[];
    const uint32_t smb = smem_u32(sb);
    const int tid = threadIdx.x, wid = tid >> 5, lane = tid & 31;
    const int blk = blockIdx.x;
    const int sh = shifted ? 4 : 0;

    // ---- load A (128 rows x 256), window-gather with roll, fp16 hi/lo split ----
    for (int g = tid; g < 4096; g += 512) {
        int t = g >> 5;
        int col0 = (g & 31) * 8;
        int tok = blk * 128 + t;
        int m = tok >> 12, w = (tok >> 6) & 63, tt = tok & 63;
        int gh = ((w >> 3) * 8 + (tt >> 3) + sh) & 63;
        int gw = ((w & 7) * 8 + (tt & 7) + sh) & 63;
        size_t idx = (size_t)((m * 64 + gh) * 64 + gw) * 256 + col0;
        uint32_t off = ((uint32_t)t * LDA + col0) * 2;
        if (!shifted) {
            const float* sp = xin + idx;
            float4 f0 = *(const float4*)sp, f1 = *(const float4*)(sp + 4);
            float fv[8] = {f0.x, f0.y, f0.z, f0.w, f1.x, f1.y, f1.z, f1.w};
            uint32_t hw[4], lw[4];
#pragma unroll
            for (int q = 0; q < 4; ++q) {
                float h0 = f16rt(fv[2 * q]), h1 = f16rt(fv[2 * q + 1]);
                hw[q] = pk(h0, h1);
                lw[q] = pk(fv[2 * q] - h0, fv[2 * q + 1] - h1);
            }
            *(uint4*)(sb + off)            = make_uint4(hw[0], hw[1], hw[2], hw[3]);
            *(uint4*)(sb + A_LO_OFF + off) = make_uint4(lw[0], lw[1], lw[2], lw[3]);
        } else {
            *(uint4*)(sb + off)            = *(const uint4*)(yh_in + idx);
            *(uint4*)(sb + A_LO_OFF + off) = *(const uint4*)(yl_in + idx);
        }
    }

    // warp grid: 4m x 4n, warp tile 32 rows x 32 cols
    const int mbase = (wid & 3) * 32;
    const int nbase = (wid >> 2) * 32;
    const int grp = lane >> 3, r8 = lane & 7;
    const int a_row = mbase + r8 + ((grp & 1) << 3);
    const int a_kof = (grp & 2) ? 8 : 0;
    const uint32_t aHi = smb + (uint32_t)(a_row * LDA + a_kof) * 2;
    const uint32_t aLo = aHi + A_LO_OFF;
    const int b_n  = r8 + ((grp & 2) << 2);
    const int b_kof = (grp & 1) ? 8 : 0;
    const uint32_t bBase = smb + GB_OFF + (uint32_t)((nbase + b_n) * 72 + b_kof) * 2;
    const int qr = lane >> 2, qc = (lane & 3) * 2;

    for (int nt = 0; nt < 6; ++nt) {
        float d[2][4][4];
#pragma unroll
        for (int mf = 0; mf < 2; ++mf)
#pragma unroll
            for (int nf = 0; nf < 4; ++nf)
#pragma unroll
                for (int q = 0; q < 4; ++q) d[mf][nf][q] = 0.f;

        // stage B chunk 0 (single fp16, 16KB -> 1024 uint4 tasks)
#pragma unroll
        for (int i = 0; i < 2; ++i) {
            int g = tid + i * 512;
            int n = g >> 3, kq = g & 7;
            uint4 v = *(const uint4*)(wqh + (size_t)(nt * 128 + n) * 256 + kq * 8);
            *(uint4*)(sb + GB_OFF + n * LDB_B + kq * 16) = v;
        }
        __syncthreads();

        for (int c = 0; c < 4; ++c) {
            uint4 stg[2];
            if (c < 3) {
#pragma unroll
                for (int i = 0; i < 2; ++i) {
                    int g = tid + i * 512;
                    int n = g >> 3, kq = g & 7;
                    stg[i] = *(const uint4*)(wqh + (size_t)(nt * 128 + n) * 256 + (c + 1) * 64 + kq * 8);
                }
            }
            const uint32_t bb0 = bBase + (uint32_t)(c & 1) * B_BUF;
#pragma unroll
            for (int kk8 = 0; kk8 < 4; ++kk8) {
                const int kg = c * 64 + kk8 * 16;
                uint32_t ah[2][4], al[2][4];
                ldsm4(ah[0], aHi + (uint32_t)kg * 2);
                ldsm4(ah[1], aHi + 16u * (LDA * 2) + (uint32_t)kg * 2);
                ldsm4(al[0], aLo + (uint32_t)kg * 2);
                ldsm4(al[1], aLo + 16u * (LDA * 2) + (uint32_t)kg * 2);
                uint32_t bh[2][4];
                const uint32_t bb = bb0 + (uint32_t)kk8 * 32;
#pragma unroll
                for (int np = 0; np < 2; ++np)
                    ldsm4(bh[np], bb + (uint32_t)np * (16 * LDB_B));
                // 2-term: (ah + al) x Wh
#pragma unroll
                for (int term = 0; term < 2; ++term)
#pragma unroll
                    for (int mf = 0; mf < 2; ++mf)
#pragma unroll
                        for (int nf = 0; nf < 4; ++nf) {
                            const int np = nf >> 1, hv = (nf & 1) * 2;
                            const uint32_t* aa = term ? al[mf] : ah[mf];
                            mma16816(d[mf][nf], aa, bh[np][hv], bh[np][hv + 1]);
                        }
            }
            if (c < 3) {
#pragma unroll
                for (int i = 0; i < 2; ++i) {
                    int g = tid + i * 512;
                    int n = g >> 3, kq = g & 7;
                    *(uint4*)(sb + GB_OFF + ((c + 1) & 1) * B_BUF + n * LDB_B + kq * 16) = stg[i];
                }
            }
            __syncthreads();
        }

        // ---- epilogue: bias, stage in dead B smem, coalesced store ----
#pragma unroll
        for (int mf = 0; mf < 2; ++mf)
#pragma unroll
            for (int h8 = 0; h8 < 2; ++h8) {
                int row = mbase + mf * 16 + h8 * 8 + qr;
#pragma unroll
                for (int nf = 0; nf < 4; ++nf) {
                    int col = nbase + nf * 8 + qc;
                    float v0 = d[mf][nf][h8 * 2]     + bias[nt * 128 + col];
                    float v1 = d[mf][nf][h8 * 2 + 1] + bias[nt * 128 + col + 1];
                    float h0 = f16rt(v0), h1 = f16rt(v1);
                    uint32_t off = (uint32_t)(row * 128 + col) * 2;
                    *(uint32_t*)(sb + GB_OFF + off)         = pk(h0, h1);
                    *(uint32_t*)(sb + GB_OFF + 32768 + off) = pk(v0 - h0, v1 - h1);
                }
            }
        __syncthreads();
#pragma unroll
        for (int i = 0; i < 4; ++i) {
            int g = tid + i * 512;               // 0..2047
            int row = g >> 4, u = g & 15;        // 16 x uint4 per 128-col row
            size_t base = (size_t)(blk * 128 + row) * 768 + nt * 128 + u * 8;
            *(uint4*)(qh_out + base) = *(const uint4*)(sb + GB_OFF + row * 256 + u * 16);
            *(uint4*)(ql_out + base) = *(const uint4*)(sb + GB_OFF + 32768 + row * 256 + u * 16);
        }
        __syncthreads();
    }
}

// ======================= fused attention + O-proj kernel (512 threads) =======================
#define LDQ  264
#define AQH  0
#define AQL  33792
#define AKH  67584
#define AKL  101376
#define AVH  135168
#define AVL  168960
#define OB   67584            // O-proj B staging (overwrites K/V areas)
#define AT_SMEM 202752

__global__ __launch_bounds__(512, 1)
void attn_fused(const __half* __restrict__ qkvh, const __half* __restrict__ qkvl,
                const __half* __restrict__ woh,
                const float* __restrict__ bo,
                __half* __restrict__ yh_out, __half* __restrict__ yl_out,
                float* __restrict__ f32_out, int shifted)
{
    extern __shared__ char sb[];
    const uint32_t smb = smem_u32(sb);
    const int tid = threadIdx.x, wid = tid >> 5, lane = tid & 31;
    const int win = blockIdx.x;
    const int wh_ = (win & 63) >> 3, ww_ = win & 7;
    const int sh = shifted ? 4 : 0;

    // ---- load pre-split qkv: straight uint4 copies (8 threads per row) ----
    {
        const int t = tid >> 3;
        const size_t rbase = (size_t)(win * 64 + t) * 768;
#pragma unroll
        for (int i = 0; i < 12; ++i) {
            int col0 = ((tid & 7) + i * 8) * 8;      // 0..760
            int sel = col0 >> 8, c = col0 & 255;
            uint32_t bh = (sel == 0) ? AQH : (sel == 1) ? AKH : AVH;
            uint32_t off = (uint32_t)(t * LDQ + c) * 2;
            *(uint4*)(sb + bh + off)         = *(const uint4*)(qkvh + rbase + col0);
            *(uint4*)(sb + bh + 33792 + off) = *(const uint4*)(qkvl + rbase + col0);
        }
    }
    __syncthreads();

    // warp task: head = wid>>1, 32-row half = wid&1
    const int head = wid >> 1;
    const int hcol = head * 32;
    const int rbase0 = (wid & 1) * 32;
    const int arow = lane & 15, acolh = (lane >> 4) * 8;
    const int grp = lane >> 3, r8 = lane & 7;
    const int b_n = r8 + ((grp & 2) << 2), b_k = (grp & 1) * 8;
    const int v_k = r8 + ((grp & 1) << 3), v_n = (grp & 2) << 2;
    const int qr = lane >> 2, qc = (lane & 3) * 2;
    const float scale = 0.17677669529663687f;

    int creg[16];
#pragma unroll
    for (int j = 0; j < 8; ++j) {
        creg[2 * j]     = regid(wh_, ww_, j * 8 + qc);
        creg[2 * j + 1] = regid(wh_, ww_, j * 8 + qc + 1);
    }

    // stream per 16-row fragment to bound live registers
#pragma unroll
    for (int fi = 0; fi < 2; ++fi) {
        const int rbase = rbase0 + fi * 16;
        uint32_t qhf[2][4], qlf[2][4];
#pragma unroll
        for (int kt = 0; kt < 2; ++kt) {
            uint32_t off = (uint32_t)((rbase + arow) * LDQ + hcol + kt * 16 + acolh) * 2;
            ldsm4(qhf[kt], smb + AQH + off);
            ldsm4(qlf[kt], smb + AQL + off);
        }

        float s[8][4];
#pragma unroll
        for (int j = 0; j < 8; ++j)
#pragma unroll
            for (int q = 0; q < 4; ++q) s[j][q] = 0.f;
#pragma unroll
        for (int kt = 0; kt < 2; ++kt)
#pragma unroll
            for (int ng = 0; ng < 4; ++ng) {
                uint32_t kh4[4], kl4[4];
                uint32_t ka = (uint32_t)((ng * 16 + b_n) * LDQ + hcol + kt * 16 + b_k) * 2;
                ldsm4(kh4, smb + AKH + ka);
                ldsm4(kl4, smb + AKL + ka);
#pragma unroll
                for (int term = 0; term < 3; ++term) {
                    const uint32_t* aa = (term == 2) ? qlf[kt] : qhf[kt];
                    const uint32_t* bv = (term == 1) ? kl4 : kh4;
                    mma16816(s[2 * ng],     aa, bv[0], bv[1]);
                    mma16816(s[2 * ng + 1], aa, bv[2], bv[3]);
                }
            }

        // scale + mask + softmax (rows rbase+qr and rbase+qr+8)
        {
            int rr0 = regid(wh_, ww_, rbase + qr);
            int rr1 = regid(wh_, ww_, rbase + qr + 8);
#pragma unroll
            for (int j = 0; j < 8; ++j) {
                s[j][0] *= scale; s[j][1] *= scale;
                s[j][2] *= scale; s[j][3] *= scale;
                if (shifted) {
                    if (creg[2 * j]     != rr0) s[j][0] += -1e9f;
                    if (creg[2 * j + 1] != rr0) s[j][1] += -1e9f;
                    if (creg[2 * j]     != rr1) s[j][2] += -1e9f;
                    if (creg[2 * j + 1] != rr1) s[j][3] += -1e9f;
                }
            }
            float m0 = -3.4e38f, m1 = -3.4e38f;
#pragma unroll
            for (int j = 0; j < 8; ++j) {
                m0 = fmaxf(m0, fmaxf(s[j][0], s[j][1]));
                m1 = fmaxf(m1, fmaxf(s[j][2], s[j][3]));
            }
            m0 = fmaxf(m0, __shfl_xor_sync(0xffffffffu, m0, 1));
            m0 = fmaxf(m0, __shfl_xor_sync(0xffffffffu, m0, 2));
            m1 = fmaxf(m1, __shfl_xor_sync(0xffffffffu, m1, 1));
            m1 = fmaxf(m1, __shfl_xor_sync(0xffffffffu, m1, 2));
            float s0 = 0.f, s1 = 0.f;
#pragma unroll
            for (int j = 0; j < 8; ++j) {
                s[j][0] = __expf(s[j][0] - m0); s0 += s[j][0];
                s[j][1] = __expf(s[j][1] - m0); s0 += s[j][1];
                s[j][2] = __expf(s[j][2] - m1); s1 += s[j][2];
                s[j][3] = __expf(s[j][3] - m1); s1 += s[j][3];
            }
            s0 += __shfl_xor_sync(0xffffffffu, s0, 1);
            s0 += __shfl_xor_sync(0xffffffffu, s0, 2);
            s1 += __shfl_xor_sync(0xffffffffu, s1, 1);
            s1 += __shfl_xor_sync(0xffffffffu, s1, 2);
            float i0 = 1.f / s0, i1 = 1.f / s1;
#pragma unroll
            for (int j = 0; j < 8; ++j) {
                s[j][0] *= i0; s[j][1] *= i0;
                s[j][2] *= i1; s[j][3] *= i1;
            }
        }

        // pack P to A-fragments (hi/lo)
        uint32_t ph[4][4], pl[4][4];
#pragma unroll
        for (int kt = 0; kt < 4; ++kt) {
            const float* e = s[2 * kt];
            const float* o2 = s[2 * kt + 1];
            float h, h2;
            h = f16rt(e[0]);  h2 = f16rt(e[1]);
            ph[kt][0] = pk(h, h2);  pl[kt][0] = pk(e[0] - h, e[1] - h2);
            h = f16rt(e[2]);  h2 = f16rt(e[3]);
            ph[kt][1] = pk(h, h2);  pl[kt][1] = pk(e[2] - h, e[3] - h2);
            h = f16rt(o2[0]); h2 = f16rt(o2[1]);
            ph[kt][2] = pk(h, h2);  pl[kt][2] = pk(o2[0] - h, o2[1] - h2);
            h = f16rt(o2[2]); h2 = f16rt(o2[3]);
            ph[kt][3] = pk(h, h2);  pl[kt][3] = pk(o2[2] - h, o2[3] - h2);
        }

        // O = P V (3-term)
        float o[4][4];
#pragma unroll
        for (int nt = 0; nt < 4; ++nt)
#pragma unroll
            for (int q = 0; q < 4; ++q) o[nt][q] = 0.f;
#pragma unroll
        for (int kt = 0; kt < 4; ++kt)
#pragma unroll
            for (int ng = 0; ng < 2; ++ng) {
                uint32_t vh4[4], vl4[4];
                uint32_t va = (uint32_t)((kt * 16 + v_k) * LDQ + hcol + ng * 16 + v_n) * 2;
                ldsm4t(vh4, smb + AVH + va);
                ldsm4t(vl4, smb + AVL + va);
#pragma unroll
                for (int term = 0; term < 3; ++term) {
                    const uint32_t* aa = (term == 2) ? pl[kt] : ph[kt];
                    const uint32_t* vv = (term == 1) ? vl4 : vh4;
                    mma16816(o[2 * ng],     aa, vv[0], vv[1]);
                    mma16816(o[2 * ng + 1], aa, vv[2], vv[3]);
                }
            }

        // store attn-out (split fp16) into dead Q smem: own rows/cols
#pragma unroll
        for (int nt = 0; nt < 4; ++nt) {
            int col = hcol + nt * 8 + qc;
            int r0 = rbase + qr;
            float v0 = o[nt][0], v1 = o[nt][1];
            float h0 = f16rt(v0), h1 = f16rt(v1);
            uint32_t off0 = (uint32_t)(r0 * LDQ + col) * 2;
            *(uint32_t*)(sb + AQH + off0) = pk(h0, h1);
            *(uint32_t*)(sb + AQL + off0) = pk(v0 - h0, v1 - h1);
            float v2 = o[nt][2], v3 = o[nt][3];
            float h2 = f16rt(v2), h3 = f16rt(v3);
            uint32_t off1 = (uint32_t)((r0 + 8) * LDQ + col) * 2;
            *(uint32_t*)(sb + AQH + off1) = pk(h2, h3);
            *(uint32_t*)(sb + AQL + off1) = pk(v2 - h2, v3 - h3);
        }
    }
    __syncthreads();   // attn-out complete; K/V smem dead

    // ======= O-projection (2-term): [64,256] = (Ah+Al) @ Wo^T; warp grid 2m x 8n =======
    const int mbase = (wid & 1) * 32;
    const int nbase = (wid >> 1) * 32;
    const uint32_t aHi = smb + AQH + (uint32_t)((mbase + r8 + ((grp & 1) << 3)) * LDQ + ((grp & 2) ? 8 : 0)) * 2;
    const uint32_t aLo = aHi + (AQL - AQH);
    const uint32_t bBase = smb + OB + (uint32_t)((nbase + b_n) * 72 + b_k) * 2;

    float d[2][4][4];
#pragma unroll
    for (int mf = 0; mf < 2; ++mf)
#pragma unroll
        for (int nf = 0; nf < 4; ++nf)
#pragma unroll
            for (int q = 0; q < 4; ++q) d[mf][nf][q] = 0.f;

    for (int c = 0; c < 4; ++c) {
        // stage B chunk [256 n][64 k] single fp16 (36864 B)
#pragma unroll
        for (int i = 0; i < 4; ++i) {
            int g = tid + i * 512;
            int n = g >> 3, kq = g & 7;
            uint4 v = *(const uint4*)(woh + (size_t)n * 256 + c * 64 + kq * 8);
            *(uint4*)(sb + OB + n * LDB_B + kq * 16) = v;
        }
        __syncthreads();
#pragma unroll
        for (int kk8 = 0; kk8 < 4; ++kk8) {
            const int kg = c * 64 + kk8 * 16;
            uint32_t ah[2][4], al[2][4];
            ldsm4(ah[0], aHi + (uint32_t)kg * 2);
            ldsm4(ah[1], aHi + 16u * (LDQ * 2) + (uint32_t)kg * 2);
            ldsm4(al[0], aLo + (uint32_t)kg * 2);
            ldsm4(al[1], aLo + 16u * (LDQ * 2) + (uint32_t)kg * 2);
            uint32_t bh4[2][4];
            const uint32_t bb = bBase + (uint32_t)kk8 * 32;
#pragma unroll
            for (int np = 0; np < 2; ++np)
                ldsm4(bh4[np], bb + (uint32_t)np * (16 * LDB_B));
#pragma unroll
            for (int term = 0; term < 2; ++term)
#pragma unroll
                for (int mf = 0; mf < 2; ++mf)
#pragma unroll
                    for (int nf = 0; nf < 4; ++nf) {
                        const int np = nf >> 1, hv = (nf & 1) * 2;
                        const uint32_t* aa = term ? al[mf] : ah[mf];
                        mma16816(d[mf][nf], aa, bh4[np][hv], bh4[np][hv + 1]);
                    }
        }
        __syncthreads();
    }

    if (!shifted) {
        // pass 1: stage split-fp16 y in dead B smem, then coalesced uint4 stores
#pragma unroll
        for (int mf = 0; mf < 2; ++mf)
#pragma unroll
            for (int h8 = 0; h8 < 2; ++h8) {
                int row = mbase + mf * 16 + h8 * 8 + qr;
#pragma unroll
                for (int nf = 0; nf < 4; ++nf) {
                    int col = nbase + nf * 8 + qc;
                    float v0 = d[mf][nf][h8 * 2]     + bo[col];
                    float v1 = d[mf][nf][h8 * 2 + 1] + bo[col + 1];
                    float h0 = f16rt(v0), h1 = f16rt(v1);
                    uint32_t off = (uint32_t)(row * 256 + col) * 2;
                    *(uint32_t*)(sb + OB + off)         = pk(h0, h1);
                    *(uint32_t*)(sb + OB + 32768 + off) = pk(v0 - h0, v1 - h1);
                }
            }
        __syncthreads();
#pragma unroll
        for (int i = 0; i < 8; ++i) {
            int g = tid + i * 512;               // 0..4095
            int half_ = g >> 11, j = g & 2047;   // 64 rows x 32 uint4
            int row = j >> 5, u = j & 31;
            int tok = win * 64 + row;
            int m = tok >> 12, w = (tok >> 6) & 63, tt = tok & 63;
            int gh = (w >> 3) * 8 + (tt >> 3);
            int gw = (w & 7) * 8 + (tt & 7);
            size_t base = (size_t)((m * 64 + gh) * 64 + gw) * 256 + u * 8;
            __half* dst = half_ ? yl_out : yh_out;
            *(uint4*)(dst + base) = *(const uint4*)(sb + OB + half_ * 32768 + row * 512 + u * 16);
        }
    } else {
        // pass 2: direct fp32 image scatter (+roll back), full-sector float2 quads
#pragma unroll
        for (int mf = 0; mf < 2; ++mf)
#pragma unroll
            for (int h8 = 0; h8 < 2; ++h8) {
                int row = mbase + mf * 16 + h8 * 8 + qr;
                int tok = win * 64 + row;
                int m = tok >> 12, w = (tok >> 6) & 63, tt = tok & 63;
                int gh = ((w >> 3) * 8 + (tt >> 3) + sh) & 63;
                int gw = ((w & 7) * 8 + (tt & 7) + sh) & 63;
                size_t base = (size_t)((m * 64 + gh) * 64 + gw) * 256;
#pragma unroll
                for (int nf = 0; nf < 4; ++nf) {
                    int col = nbase + nf * 8 + qc;
                    float v0 = d[mf][nf][h8 * 2]     + bo[col];
                    float v1 = d[mf][nf][h8 * 2 + 1] + bo[col + 1];
                    *(float2*)(f32_out + base + col) = make_float2(v0, v1);
                }
            }
    }
}

// ======================= launch =======================
extern "C" void kernel_launch(void* const* d_in, const int* in_sizes, int n_in,
                              void* d_out, int out_size) {
    (void)in_sizes; (void)n_in; (void)out_size;
    const float* x    = (const float*)d_in[0];
    const float* wqkv = (const float*)d_in[1];
    const float* bqkv = (const float*)d_in[2];
    const float* wo   = (const float*)d_in[3];
    const float* bo   = (const float*)d_in[4];
    float* out = (float*)d_out;

    cudaFuncSetAttribute(gemm_qkv,   cudaFuncAttributeMaxDynamicSharedMemorySize, GS_SMEM);
    cudaFuncSetAttribute(attn_fused, cudaFuncAttributeMaxDynamicSharedMemorySize, AT_SMEM);

    __half *wqh, *woh, *qh, *ql, *yh, *yl;
    cudaGetSymbolAddress((void**)&wqh, g_wtq_h);
    cudaGetSymbolAddress((void**)&woh, g_wto_h);
    cudaGetSymbolAddress((void**)&qh,  g_qkvh);
    cudaGetSymbolAddress((void**)&ql,  g_qkvl);
    cudaGetSymbolAddress((void**)&yh,  g_yh);
    cudaGetSymbolAddress((void**)&yl,  g_yl);

    prep_kernel<<<1024, 256>>>(wqkv, wo);

    for (int pass = 0; pass < 2; ++pass) {
        gemm_qkv<<<1024, 512, GS_SMEM>>>(x, yh, yl, wqh, bqkv, qh, ql, pass);
        attn_fused<<<2048, 512, AT_SMEM>>>(qh, ql, woh, bo, yh, yl, out, pass);
    }
}

// round 15
// speedup vs baseline: 1.5293x; 1.1503x over previous
#include <cuda_runtime.h>
#include <cuda_fp16.h>
#include <cstdint>

// Swin layer: fp16 HMMA GEMMs + fused flash-attention + O-proj.
// R15: QKV GEMM 1-term (A single fp16: x pass1 / y pass2); qkv output kept
// split so attention numerics unchanged; y stored single.
#define NTOK 131072          // 32 * 64 * 64 tokens

// -------- device scratch (allocation-free rule) --------
__device__ __half g_qkvh[(size_t)NTOK * 768];
__device__ __half g_qkvl[(size_t)NTOK * 768];
__device__ __half g_y[NTOK * 256];       // pass-1 output, image layout, single fp16
__device__ __half g_wtq_h[768 * 256];    // W_qkv^T [N][K], single fp16
__device__ __half g_wto_h[256 * 256];    // W_o^T   [N][K], single fp16

// ======================= helpers =======================
__device__ __forceinline__ uint32_t smem_u32(const void* p) {
    uint32_t a;
    asm("{ .reg .u64 t; cvta.to.shared.u64 t, %1; cvt.u32.u64 %0, t; }" : "=r"(a) : "l"(p));
    return a;
}
__device__ __forceinline__ void ldsm4(uint32_t r[4], uint32_t addr) {
    asm volatile("ldmatrix.sync.aligned.m8n8.x4.shared.b16 {%0,%1,%2,%3}, [%4];"
                 : "=r"(r[0]), "=r"(r[1]), "=r"(r[2]), "=r"(r[3]) : "r"(addr));
}
__device__ __forceinline__ void ldsm4t(uint32_t r[4], uint32_t addr) {
    asm volatile("ldmatrix.sync.aligned.m8n8.x4.trans.shared.b16 {%0,%1,%2,%3}, [%4];"
                 : "=r"(r[0]), "=r"(r[1]), "=r"(r[2]), "=r"(r[3]) : "r"(addr));
}
__device__ __forceinline__ void mma16816(float d[4], const uint32_t a[4],
                                         uint32_t b0, uint32_t b1) {
    asm volatile(
        "mma.sync.aligned.m16n8k16.row.col.f32.f16.f16.f32 "
        "{%0,%1,%2,%3}, {%4,%5,%6,%7}, {%8,%9}, {%0,%1,%2,%3};"
        : "+f"(d[0]), "+f"(d[1]), "+f"(d[2]), "+f"(d[3])
        : "r"(a[0]), "r"(a[1]), "r"(a[2]), "r"(a[3]), "r"(b0), "r"(b1));
}
__device__ __forceinline__ uint32_t pk(float c0, float c1) {   // f16x2(lo=c0, hi=c1)
    uint32_t d;
    asm("cvt.rn.f16x2.f32 %0, %1, %2;" : "=r"(d) : "f"(c1), "f"(c0));
    return d;
}
__device__ __forceinline__ float f16rt(float v) {   // round-trip through fp16
    return __half2float(__float2half_rn(v));
}
__device__ __forceinline__ int regid(int wh, int ww, int t) {
    int r = t >> 3, c = t & 7;
    int hr = (wh == 7) ? ((r < 4) ? 1 : 2) : 0;
    int wr = (ww == 7) ? ((c < 4) ? 1 : 2) : 0;
    return hr * 3 + wr;
}

// ======================= prep: W^T fp16 singles =======================
__global__ void prep_kernel(const float* __restrict__ wqkv, const float* __restrict__ wo) {
    int i = blockIdx.x * blockDim.x + threadIdx.x;
    if (i < 768 * 256) {
        int n = i >> 8, k = i & 255;
        g_wtq_h[i] = __float2half_rn(wqkv[k * 768 + n]);
    } else if (i < 768 * 256 + 256 * 256) {
        int j = i - 768 * 256;
        int n = j >> 8, k = j & 255;
        g_wto_h[j] = __float2half_rn(wo[k * 256 + n]);
    }
}

// ======================= QKV GEMM kernel (512 threads, 1-term) =======================
#define LDA      264
#define GB_OFF   67584               // A single buffer: 128*264*2
#define B_BUF    18432               // one 128n x 64k fp16 chunk (stride 72)
#define LDB_B    144
#define GS_SMEM  (GB_OFF + 65536)    // B bufs (2x18432) OR epilogue staging (64KB)

__global__ __launch_bounds__(512, 1)
void gemm_qkv(const float* __restrict__ xin,
              const __half* __restrict__ y_in,
              const __half* __restrict__ wqh,
              const float* __restrict__ bias,
              __half* __restrict__ qh_out, __half* __restrict__ ql_out,
              int shifted)
{
    extern __shared__ char sb[];
    const uint32_t smb = smem_u32(sb);
    const int tid = threadIdx.x, wid = tid >> 5, lane = tid & 31;
    const int blk = blockIdx.x;
    const int sh = shifted ? 4 : 0;

    // ---- load A (128 rows x 256), window-gather with roll, single fp16 ----
    for (int g = tid; g < 4096; g += 512) {
        int t = g >> 5;
        int col0 = (g & 31) * 8;
        int tok = blk * 128 + t;
        int m = tok >> 12, w = (tok >> 6) & 63, tt = tok & 63;
        int gh = ((w >> 3) * 8 + (tt >> 3) + sh) & 63;
        int gw = ((w & 7) * 8 + (tt & 7) + sh) & 63;
        size_t idx = (size_t)((m * 64 + gh) * 64 + gw) * 256 + col0;
        uint32_t off = ((uint32_t)t * LDA + col0) * 2;
        if (!shifted) {
            const float* sp = xin + idx;
            float4 f0 = *(const float4*)sp, f1 = *(const float4*)(sp + 4);
            uint32_t hw[4];
            hw[0] = pk(f0.x, f0.y); hw[1] = pk(f0.z, f0.w);
            hw[2] = pk(f1.x, f1.y); hw[3] = pk(f1.z, f1.w);
            *(uint4*)(sb + off) = make_uint4(hw[0], hw[1], hw[2], hw[3]);
        } else {
            *(uint4*)(sb + off) = *(const uint4*)(y_in + idx);
        }
    }

    // warp grid: 4m x 4n, warp tile 32 rows x 32 cols
    const int mbase = (wid & 3) * 32;
    const int nbase = (wid >> 2) * 32;
    const int grp = lane >> 3, r8 = lane & 7;
    const int a_row = mbase + r8 + ((grp & 1) << 3);
    const int a_kof = (grp & 2) ? 8 : 0;
    const uint32_t aHi = smb + (uint32_t)(a_row * LDA + a_kof) * 2;
    const int b_n  = r8 + ((grp & 2) << 2);
    const int b_kof = (grp & 1) ? 8 : 0;
    const uint32_t bBase = smb + GB_OFF + (uint32_t)((nbase + b_n) * 72 + b_kof) * 2;
    const int qr = lane >> 2, qc = (lane & 3) * 2;

    for (int nt = 0; nt < 6; ++nt) {
        float d[2][4][4];
#pragma unroll
        for (int mf = 0; mf < 2; ++mf)
#pragma unroll
            for (int nf = 0; nf < 4; ++nf)
#pragma unroll
                for (int q = 0; q < 4; ++q) d[mf][nf][q] = 0.f;

        // stage B chunk 0 (single fp16, 16KB -> 1024 uint4 tasks)
#pragma unroll
        for (int i = 0; i < 2; ++i) {
            int g = tid + i * 512;
            int n = g >> 3, kq = g & 7;
            uint4 v = *(const uint4*)(wqh + (size_t)(nt * 128 + n) * 256 + kq * 8);
            *(uint4*)(sb + GB_OFF + n * LDB_B + kq * 16) = v;
        }
        __syncthreads();

        for (int c = 0; c < 4; ++c) {
            uint4 stg[2];
            if (c < 3) {
#pragma unroll
                for (int i = 0; i < 2; ++i) {
                    int g = tid + i * 512;
                    int n = g >> 3, kq = g & 7;
                    stg[i] = *(const uint4*)(wqh + (size_t)(nt * 128 + n) * 256 + (c + 1) * 64 + kq * 8);
                }
            }
            const uint32_t bb0 = bBase + (uint32_t)(c & 1) * B_BUF;
#pragma unroll
            for (int kk8 = 0; kk8 < 4; ++kk8) {
                const int kg = c * 64 + kk8 * 16;
                uint32_t ah[2][4];
                ldsm4(ah[0], aHi + (uint32_t)kg * 2);
                ldsm4(ah[1], aHi + 16u * (LDA * 2) + (uint32_t)kg * 2);
                uint32_t bh[2][4];
                const uint32_t bb = bb0 + (uint32_t)kk8 * 32;
#pragma unroll
                for (int np = 0; np < 2; ++np)
                    ldsm4(bh[np], bb + (uint32_t)np * (16 * LDB_B));
                // 1-term: A single x W single
#pragma unroll
                for (int mf = 0; mf < 2; ++mf)
#pragma unroll
                    for (int nf = 0; nf < 4; ++nf) {
                        const int np = nf >> 1, hv = (nf & 1) * 2;
                        mma16816(d[mf][nf], ah[mf], bh[np][hv], bh[np][hv + 1]);
                    }
            }
            if (c < 3) {
#pragma unroll
                for (int i = 0; i < 2; ++i) {
                    int g = tid + i * 512;
                    int n = g >> 3, kq = g & 7;
                    *(uint4*)(sb + GB_OFF + ((c + 1) & 1) * B_BUF + n * LDB_B + kq * 16) = stg[i];
                }
            }
            __syncthreads();
        }

        // ---- epilogue: bias, split-fp16 staging in dead B smem, coalesced store ----
#pragma unroll
        for (int mf = 0; mf < 2; ++mf)
#pragma unroll
            for (int h8 = 0; h8 < 2; ++h8) {
                int row = mbase + mf * 16 + h8 * 8 + qr;
#pragma unroll
                for (int nf = 0; nf < 4; ++nf) {
                    int col = nbase + nf * 8 + qc;
                    float v0 = d[mf][nf][h8 * 2]     + bias[nt * 128 + col];
                    float v1 = d[mf][nf][h8 * 2 + 1] + bias[nt * 128 + col + 1];
                    float h0 = f16rt(v0), h1 = f16rt(v1);
                    uint32_t off = (uint32_t)(row * 128 + col) * 2;
                    *(uint32_t*)(sb + GB_OFF + off)         = pk(h0, h1);
                    *(uint32_t*)(sb + GB_OFF + 32768 + off) = pk(v0 - h0, v1 - h1);
                }
            }
        __syncthreads();
#pragma unroll
        for (int i = 0; i < 4; ++i) {
            int g = tid + i * 512;               // 0..2047
            int row = g >> 4, u = g & 15;        // 16 x uint4 per 128-col row
            size_t base = (size_t)(blk * 128 + row) * 768 + nt * 128 + u * 8;
            *(uint4*)(qh_out + base) = *(const uint4*)(sb + GB_OFF + row * 256 + u * 16);
            *(uint4*)(ql_out + base) = *(const uint4*)(sb + GB_OFF + 32768 + row * 256 + u * 16);
        }
        __syncthreads();
    }
}

// ======================= fused attention + O-proj kernel (512 threads) =======================
#define LDQ  264
#define AQH  0
#define AQL  33792
#define AKH  67584
#define AKL  101376
#define AVH  135168
#define AVL  168960
#define OB   67584            // O-proj B staging (overwrites K/V areas)
#define AT_SMEM 202752

__global__ __launch_bounds__(512, 1)
void attn_fused(const __half* __restrict__ qkvh, const __half* __restrict__ qkvl,
                const __half* __restrict__ woh,
                const float* __restrict__ bo,
                __half* __restrict__ y_out,
                float* __restrict__ f32_out, int shifted)
{
    extern __shared__ char sb[];
    const uint32_t smb = smem_u32(sb);
    const int tid = threadIdx.x, wid = tid >> 5, lane = tid & 31;
    const int win = blockIdx.x;
    const int wh_ = (win & 63) >> 3, ww_ = win & 7;
    const int sh = shifted ? 4 : 0;

    // ---- load pre-split qkv: straight uint4 copies (8 threads per row) ----
    {
        const int t = tid >> 3;
        const size_t rbase = (size_t)(win * 64 + t) * 768;
#pragma unroll
        for (int i = 0; i < 12; ++i) {
            int col0 = ((tid & 7) + i * 8) * 8;      // 0..760
            int sel = col0 >> 8, c = col0 & 255;
            uint32_t bh = (sel == 0) ? AQH : (sel == 1) ? AKH : AVH;
            uint32_t off = (uint32_t)(t * LDQ + c) * 2;
            *(uint4*)(sb + bh + off)         = *(const uint4*)(qkvh + rbase + col0);
            *(uint4*)(sb + bh + 33792 + off) = *(const uint4*)(qkvl + rbase + col0);
        }
    }
    __syncthreads();

    // warp task: head = wid>>1, 32-row half = wid&1
    const int head = wid >> 1;
    const int hcol = head * 32;
    const int rbase0 = (wid & 1) * 32;
    const int arow = lane & 15, acolh = (lane >> 4) * 8;
    const int grp = lane >> 3, r8 = lane & 7;
    const int b_n = r8 + ((grp & 2) << 2), b_k = (grp & 1) * 8;
    const int v_k = r8 + ((grp & 1) << 3), v_n = (grp & 2) << 2;
    const int qr = lane >> 2, qc = (lane & 3) * 2;
    const float scale = 0.17677669529663687f;

    int creg[16];
#pragma unroll
    for (int j = 0; j < 8; ++j) {
        creg[2 * j]     = regid(wh_, ww_, j * 8 + qc);
        creg[2 * j + 1] = regid(wh_, ww_, j * 8 + qc + 1);
    }

    // stream per 16-row fragment to bound live registers
#pragma unroll
    for (int fi = 0; fi < 2; ++fi) {
        const int rbase = rbase0 + fi * 16;
        uint32_t qhf[2][4], qlf[2][4];
#pragma unroll
        for (int kt = 0; kt < 2; ++kt) {
            uint32_t off = (uint32_t)((rbase + arow) * LDQ + hcol + kt * 16 + acolh) * 2;
            ldsm4(qhf[kt], smb + AQH + off);
            ldsm4(qlf[kt], smb + AQL + off);
        }

        float s[8][4];
#pragma unroll
        for (int j = 0; j < 8; ++j)
#pragma unroll
            for (int q = 0; q < 4; ++q) s[j][q] = 0.f;
#pragma unroll
        for (int kt = 0; kt < 2; ++kt)
#pragma unroll
            for (int ng = 0; ng < 4; ++ng) {
                uint32_t kh4[4], kl4[4];
                uint32_t ka = (uint32_t)((ng * 16 + b_n) * LDQ + hcol + kt * 16 + b_k) * 2;
                ldsm4(kh4, smb + AKH + ka);
                ldsm4(kl4, smb + AKL + ka);
#pragma unroll
                for (int term = 0; term < 3; ++term) {
                    const uint32_t* aa = (term == 2) ? qlf[kt] : qhf[kt];
                    const uint32_t* bv = (term == 1) ? kl4 : kh4;
                    mma16816(s[2 * ng],     aa, bv[0], bv[1]);
                    mma16816(s[2 * ng + 1], aa, bv[2], bv[3]);
                }
            }

        // scale + mask + softmax (rows rbase+qr and rbase+qr+8)
        {
            int rr0 = regid(wh_, ww_, rbase + qr);
            int rr1 = regid(wh_, ww_, rbase + qr + 8);
#pragma unroll
            for (int j = 0; j < 8; ++j) {
                s[j][0] *= scale; s[j][1] *= scale;
                s[j][2] *= scale; s[j][3] *= scale;
                if (shifted) {
                    if (creg[2 * j]     != rr0) s[j][0] += -1e9f;
                    if (creg[2 * j + 1] != rr0) s[j][1] += -1e9f;
                    if (creg[2 * j]     != rr1) s[j][2] += -1e9f;
                    if (creg[2 * j + 1] != rr1) s[j][3] += -1e9f;
                }
            }
            float m0 = -3.4e38f, m1 = -3.4e38f;
#pragma unroll
            for (int j = 0; j < 8; ++j) {
                m0 = fmaxf(m0, fmaxf(s[j][0], s[j][1]));
                m1 = fmaxf(m1, fmaxf(s[j][2], s[j][3]));
            }
            m0 = fmaxf(m0, __shfl_xor_sync(0xffffffffu, m0, 1));
            m0 = fmaxf(m0, __shfl_xor_sync(0xffffffffu, m0, 2));
            m1 = fmaxf(m1, __shfl_xor_sync(0xffffffffu, m1, 1));
            m1 = fmaxf(m1, __shfl_xor_sync(0xffffffffu, m1, 2));
            float s0 = 0.f, s1 = 0.f;
#pragma unroll
            for (int j = 0; j < 8; ++j) {
                s[j][0] = __expf(s[j][0] - m0); s0 += s[j][0];
                s[j][1] = __expf(s[j][1] - m0); s0 += s[j][1];
                s[j][2] = __expf(s[j][2] - m1); s1 += s[j][2];
                s[j][3] = __expf(s[j][3] - m1); s1 += s[j][3];
            }
            s0 += __shfl_xor_sync(0xffffffffu, s0, 1);
            s0 += __shfl_xor_sync(0xffffffffu, s0, 2);
            s1 += __shfl_xor_sync(0xffffffffu, s1, 1);
            s1 += __shfl_xor_sync(0xffffffffu, s1, 2);
            float i0 = 1.f / s0, i1 = 1.f / s1;
#pragma unroll
            for (int j = 0; j < 8; ++j) {
                s[j][0] *= i0; s[j][1] *= i0;
                s[j][2] *= i1; s[j][3] *= i1;
            }
        }

        // pack P to A-fragments (hi/lo)
        uint32_t ph[4][4], pl[4][4];
#pragma unroll
        for (int kt = 0; kt < 4; ++kt) {
            const float* e = s[2 * kt];
            const float* o2 = s[2 * kt + 1];
            float h, h2;
            h = f16rt(e[0]);  h2 = f16rt(e[1]);
            ph[kt][0] = pk(h, h2);  pl[kt][0] = pk(e[0] - h, e[1] - h2);
            h = f16rt(e[2]);  h2 = f16rt(e[3]);
            ph[kt][1] = pk(h, h2);  pl[kt][1] = pk(e[2] - h, e[3] - h2);
            h = f16rt(o2[0]); h2 = f16rt(o2[1]);
            ph[kt][2] = pk(h, h2);  pl[kt][2] = pk(o2[0] - h, o2[1] - h2);
            h = f16rt(o2[2]); h2 = f16rt(o2[3]);
            ph[kt][3] = pk(h, h2);  pl[kt][3] = pk(o2[2] - h, o2[3] - h2);
        }

        // O = P V (3-term)
        float o[4][4];
#pragma unroll
        for (int nt = 0; nt < 4; ++nt)
#pragma unroll
            for (int q = 0; q < 4; ++q) o[nt][q] = 0.f;
#pragma unroll
        for (int kt = 0; kt < 4; ++kt)
#pragma unroll
            for (int ng = 0; ng < 2; ++ng) {
                uint32_t vh4[4], vl4[4];
                uint32_t va = (uint32_t)((kt * 16 + v_k) * LDQ + hcol + ng * 16 + v_n) * 2;
                ldsm4t(vh4, smb + AVH + va);
                ldsm4t(vl4, smb + AVL + va);
#pragma unroll
                for (int term = 0; term < 3; ++term) {
                    const uint32_t* aa = (term == 2) ? pl[kt] : ph[kt];
                    const uint32_t* vv = (term == 1) ? vl4 : vh4;
                    mma16816(o[2 * ng],     aa, vv[0], vv[1]);
                    mma16816(o[2 * ng + 1], aa, vv[2], vv[3]);
                }
            }

        // store attn-out (split fp16) into dead Q smem: own rows/cols
#pragma unroll
        for (int nt = 0; nt < 4; ++nt) {
            int col = hcol + nt * 8 + qc;
            int r0 = rbase + qr;
            float v0 = o[nt][0], v1 = o[nt][1];
            float h0 = f16rt(v0), h1 = f16rt(v1);
            uint32_t off0 = (uint32_t)(r0 * LDQ + col) * 2;
            *(uint32_t*)(sb + AQH + off0) = pk(h0, h1);
            *(uint32_t*)(sb + AQL + off0) = pk(v0 - h0, v1 - h1);
            float v2 = o[nt][2], v3 = o[nt][3];
            float h2 = f16rt(v2), h3 = f16rt(v3);
            uint32_t off1 = (uint32_t)((r0 + 8) * LDQ + col) * 2;
            *(uint32_t*)(sb + AQH + off1) = pk(h2, h3);
            *(uint32_t*)(sb + AQL + off1) = pk(v2 - h2, v3 - h3);
        }
    }
    __syncthreads();   // attn-out complete; K/V smem dead

    // ======= O-projection (2-term): [64,256] = (Ah+Al) @ Wo^T; warp grid 2m x 8n =======
    const int mbase = (wid & 1) * 32;
    const int nbase = (wid >> 1) * 32;
    const uint32_t aHi = smb + AQH + (uint32_t)((mbase + r8 + ((grp & 1) << 3)) * LDQ + ((grp & 2) ? 8 : 0)) * 2;
    const uint32_t aLo = aHi + (AQL - AQH);
    const uint32_t bBase = smb + OB + (uint32_t)((nbase + b_n) * 72 + b_k) * 2;

    float d[2][4][4];
#pragma unroll
    for (int mf = 0; mf < 2; ++mf)
#pragma unroll
        for (int nf = 0; nf < 4; ++nf)
#pragma unroll
            for (int q = 0; q < 4; ++q) d[mf][nf][q] = 0.f;

    for (int c = 0; c < 4; ++c) {
        // stage B chunk [256 n][64 k] single fp16 (36864 B)
#pragma unroll
        for (int i = 0; i < 4; ++i) {
            int g = tid + i * 512;
            int n = g >> 3, kq = g & 7;
            uint4 v = *(const uint4*)(woh + (size_t)n * 256 + c * 64 + kq * 8);
            *(uint4*)(sb + OB + n * LDB_B + kq * 16) = v;
        }
        __syncthreads();
#pragma unroll
        for (int kk8 = 0; kk8 < 4; ++kk8) {
            const int kg = c * 64 + kk8 * 16;
            uint32_t ah[2][4], al[2][4];
            ldsm4(ah[0], aHi + (uint32_t)kg * 2);
            ldsm4(ah[1], aHi + 16u * (LDQ * 2) + (uint32_t)kg * 2);
            ldsm4(al[0], aLo + (uint32_t)kg * 2);
            ldsm4(al[1], aLo + 16u * (LDQ * 2) + (uint32_t)kg * 2);
            uint32_t bh4[2][4];
            const uint32_t bb = bBase + (uint32_t)kk8 * 32;
#pragma unroll
            for (int np = 0; np < 2; ++np)
                ldsm4(bh4[np], bb + (uint32_t)np * (16 * LDB_B));
#pragma unroll
            for (int term = 0; term < 2; ++term)
#pragma unroll
                for (int mf = 0; mf < 2; ++mf)
#pragma unroll
                    for (int nf = 0; nf < 4; ++nf) {
                        const int np = nf >> 1, hv = (nf & 1) * 2;
                        const uint32_t* aa = term ? al[mf] : ah[mf];
                        mma16816(d[mf][nf], aa, bh4[np][hv], bh4[np][hv + 1]);
                    }
        }
        __syncthreads();
    }

    if (!shifted) {
        // pass 1: stage single-fp16 y in dead B smem, then coalesced uint4 stores
#pragma unroll
        for (int mf = 0; mf < 2; ++mf)
#pragma unroll
            for (int h8 = 0; h8 < 2; ++h8) {
                int row = mbase + mf * 16 + h8 * 8 + qr;
#pragma unroll
                for (int nf = 0; nf < 4; ++nf) {
                    int col = nbase + nf * 8 + qc;
                    float v0 = d[mf][nf][h8 * 2]     + bo[col];
                    float v1 = d[mf][nf][h8 * 2 + 1] + bo[col + 1];
                    uint32_t off = (uint32_t)(row * 256 + col) * 2;
                    *(uint32_t*)(sb + OB + off) = pk(v0, v1);
                }
            }
        __syncthreads();
#pragma unroll
        for (int i = 0; i < 4; ++i) {
            int g = tid + i * 512;               // 0..2047: 64 rows x 32 uint4
            int row = g >> 5, u = g & 31;
            int tok = win * 64 + row;
            int m = tok >> 12, w = (tok >> 6) & 63, tt = tok & 63;
            int gh = (w >> 3) * 8 + (tt >> 3);
            int gw = (w & 7) * 8 + (tt & 7);
            size_t base = (size_t)((m * 64 + gh) * 64 + gw) * 256 + u * 8;
            *(uint4*)(y_out + base) = *(const uint4*)(sb + OB + row * 512 + u * 16);
        }
    } else {
        // pass 2: direct fp32 image scatter (+roll back), full-sector float2 quads
#pragma unroll
        for (int mf = 0; mf < 2; ++mf)
#pragma unroll
            for (int h8 = 0; h8 < 2; ++h8) {
                int row = mbase + mf * 16 + h8 * 8 + qr;
                int tok = win * 64 + row;
                int m = tok >> 12, w = (tok >> 6) & 63, tt = tok & 63;
                int gh = ((w >> 3) * 8 + (tt >> 3) + sh) & 63;
                int gw = ((w & 7) * 8 + (tt & 7) + sh) & 63;
                size_t base = (size_t)((m * 64 + gh) * 64 + gw) * 256;
#pragma unroll
                for (int nf = 0; nf < 4; ++nf) {
                    int col = nbase + nf * 8 + qc;
                    float v0 = d[mf][nf][h8 * 2]     + bo[col];
                    float v1 = d[mf][nf][h8 * 2 + 1] + bo[col + 1];
                    *(float2*)(f32_out + base + col) = make_float2(v0, v1);
                }
            }
    }
}

// ======================= launch =======================
extern "C" void kernel_launch(void* const* d_in, const int* in_sizes, int n_in,
                              void* d_out, int out_size) {
    (void)in_sizes; (void)n_in; (void)out_size;
    const float* x    = (const float*)d_in[0];
    const float* wqkv = (const float*)d_in[1];
    const float* bqkv = (const float*)d_in[2];
    const float* wo   = (const float*)d_in[3];
    const float* bo   = (const float*)d_in[4];
    float* out = (float*)d_out;

    cudaFuncSetAttribute(gemm_qkv,   cudaFuncAttributeMaxDynamicSharedMemorySize, GS_SMEM);
    cudaFuncSetAttribute(attn_fused, cudaFuncAttributeMaxDynamicSharedMemorySize, AT_SMEM);

    __half *wqh, *woh, *qh, *ql, *yv;
    cudaGetSymbolAddress((void**)&wqh, g_wtq_h);
    cudaGetSymbolAddress((void**)&woh, g_wto_h);
    cudaGetSymbolAddress((void**)&qh,  g_qkvh);
    cudaGetSymbolAddress((void**)&ql,  g_qkvl);
    cudaGetSymbolAddress((void**)&yv,  g_y);

    prep_kernel<<<1024, 256>>>(wqkv, wo);

    for (int pass = 0; pass < 2; ++pass) {
        gemm_qkv<<<1024, 512, GS_SMEM>>>(x, yv, wqh, bqkv, qh, ql, pass);
        attn_fused<<<2048, 512, AT_SMEM>>>(qh, ql, woh, bo, yv, out, pass);
    }
}

// round 16
// speedup vs baseline: 2.0329x; 1.3293x over previous
#include <cuda_runtime.h>
#include <cuda_fp16.h>
#include <cstdint>

// Swin layer: fp16 HMMA GEMMs + fused flash-attention + O-proj.
// R16: qkv stored SINGLE fp16 (halves the dominant global round-trip);
// QK 1-term, PV 2-term (P split in regs), attn-out split in smem so
// O-proj numerics unchanged.
#define NTOK 131072          // 32 * 64 * 64 tokens

// -------- device scratch (allocation-free rule) --------
__device__ __half g_qkv[(size_t)NTOK * 768];   // single fp16
__device__ __half g_y[NTOK * 256];             // pass-1 output, image layout
__device__ __half g_wtq_h[768 * 256];          // W_qkv^T [N][K], single fp16
__device__ __half g_wto_h[256 * 256];          // W_o^T   [N][K], single fp16

// ======================= helpers =======================
__device__ __forceinline__ uint32_t smem_u32(const void* p) {
    uint32_t a;
    asm("{ .reg .u64 t; cvta.to.shared.u64 t, %1; cvt.u32.u64 %0, t; }" : "=r"(a) : "l"(p));
    return a;
}
__device__ __forceinline__ void ldsm4(uint32_t r[4], uint32_t addr) {
    asm volatile("ldmatrix.sync.aligned.m8n8.x4.shared.b16 {%0,%1,%2,%3}, [%4];"
                 : "=r"(r[0]), "=r"(r[1]), "=r"(r[2]), "=r"(r[3]) : "r"(addr));
}
__device__ __forceinline__ void ldsm4t(uint32_t r[4], uint32_t addr) {
    asm volatile("ldmatrix.sync.aligned.m8n8.x4.trans.shared.b16 {%0,%1,%2,%3}, [%4];"
                 : "=r"(r[0]), "=r"(r[1]), "=r"(r[2]), "=r"(r[3]) : "r"(addr));
}
__device__ __forceinline__ void mma16816(float d[4], const uint32_t a[4],
                                         uint32_t b0, uint32_t b1) {
    asm volatile(
        "mma.sync.aligned.m16n8k16.row.col.f32.f16.f16.f32 "
        "{%0,%1,%2,%3}, {%4,%5,%6,%7}, {%8,%9}, {%0,%1,%2,%3};"
        : "+f"(d[0]), "+f"(d[1]), "+f"(d[2]), "+f"(d[3])
        : "r"(a[0]), "r"(a[1]), "r"(a[2]), "r"(a[3]), "r"(b0), "r"(b1));
}
__device__ __forceinline__ uint32_t pk(float c0, float c1) {   // f16x2(lo=c0, hi=c1)
    uint32_t d;
    asm("cvt.rn.f16x2.f32 %0, %1, %2;" : "=r"(d) : "f"(c1), "f"(c0));
    return d;
}
__device__ __forceinline__ float f16rt(float v) {
    return __half2float(__float2half_rn(v));
}
__device__ __forceinline__ int regid(int wh, int ww, int t) {
    int r = t >> 3, c = t & 7;
    int hr = (wh == 7) ? ((r < 4) ? 1 : 2) : 0;
    int wr = (ww == 7) ? ((c < 4) ? 1 : 2) : 0;
    return hr * 3 + wr;
}

// ======================= prep: W^T fp16 singles =======================
__global__ void prep_kernel(const float* __restrict__ wqkv, const float* __restrict__ wo) {
    int i = blockIdx.x * blockDim.x + threadIdx.x;
    if (i < 768 * 256) {
        int n = i >> 8, k = i & 255;
        g_wtq_h[i] = __float2half_rn(wqkv[k * 768 + n]);
    } else if (i < 768 * 256 + 256 * 256) {
        int j = i - 768 * 256;
        int n = j >> 8, k = j & 255;
        g_wto_h[j] = __float2half_rn(wo[k * 256 + n]);
    }
}

// ======================= QKV GEMM kernel (512 threads, 1-term, single out) ==========
#define LDA      264
#define GB_OFF   67584               // A single buffer: 128*264*2
#define B_BUF    18432               // one 128n x 64k fp16 chunk (stride 72)
#define LDB_B    144
#define GS_SMEM  (GB_OFF + 65536)

__global__ __launch_bounds__(512, 1)
void gemm_qkv(const float* __restrict__ xin,
              const __half* __restrict__ y_in,
              const __half* __restrict__ wqh,
              const float* __restrict__ bias,
              __half* __restrict__ q_out,
              int shifted)
{
    extern __shared__ char sb[];
    const uint32_t smb = smem_u32(sb);
    const int tid = threadIdx.x, wid = tid >> 5, lane = tid & 31;
    const int blk = blockIdx.x;
    const int sh = shifted ? 4 : 0;

    // ---- load A (128 rows x 256), window-gather with roll, single fp16 ----
    for (int g = tid; g < 4096; g += 512) {
        int t = g >> 5;
        int col0 = (g & 31) * 8;
        int tok = blk * 128 + t;
        int m = tok >> 12, w = (tok >> 6) & 63, tt = tok & 63;
        int gh = ((w >> 3) * 8 + (tt >> 3) + sh) & 63;
        int gw = ((w & 7) * 8 + (tt & 7) + sh) & 63;
        size_t idx = (size_t)((m * 64 + gh) * 64 + gw) * 256 + col0;
        uint32_t off = ((uint32_t)t * LDA + col0) * 2;
        if (!shifted) {
            const float* sp = xin + idx;
            float4 f0 = *(const float4*)sp, f1 = *(const float4*)(sp + 4);
            uint32_t hw[4];
            hw[0] = pk(f0.x, f0.y); hw[1] = pk(f0.z, f0.w);
            hw[2] = pk(f1.x, f1.y); hw[3] = pk(f1.z, f1.w);
            *(uint4*)(sb + off) = make_uint4(hw[0], hw[1], hw[2], hw[3]);
        } else {
            *(uint4*)(sb + off) = *(const uint4*)(y_in + idx);
        }
    }

    // warp grid: 4m x 4n, warp tile 32 rows x 32 cols
    const int mbase = (wid & 3) * 32;
    const int nbase = (wid >> 2) * 32;
    const int grp = lane >> 3, r8 = lane & 7;
    const int a_row = mbase + r8 + ((grp & 1) << 3);
    const int a_kof = (grp & 2) ? 8 : 0;
    const uint32_t aHi = smb + (uint32_t)(a_row * LDA + a_kof) * 2;
    const int b_n  = r8 + ((grp & 2) << 2);
    const int b_kof = (grp & 1) ? 8 : 0;
    const uint32_t bBase = smb + GB_OFF + (uint32_t)((nbase + b_n) * 72 + b_kof) * 2;
    const int qr = lane >> 2, qc = (lane & 3) * 2;

    for (int nt = 0; nt < 6; ++nt) {
        float d[2][4][4];
#pragma unroll
        for (int mf = 0; mf < 2; ++mf)
#pragma unroll
            for (int nf = 0; nf < 4; ++nf)
#pragma unroll
                for (int q = 0; q < 4; ++q) d[mf][nf][q] = 0.f;

#pragma unroll
        for (int i = 0; i < 2; ++i) {
            int g = tid + i * 512;
            int n = g >> 3, kq = g & 7;
            uint4 v = *(const uint4*)(wqh + (size_t)(nt * 128 + n) * 256 + kq * 8);
            *(uint4*)(sb + GB_OFF + n * LDB_B + kq * 16) = v;
        }
        __syncthreads();

        for (int c = 0; c < 4; ++c) {
            uint4 stg[2];
            if (c < 3) {
#pragma unroll
                for (int i = 0; i < 2; ++i) {
                    int g = tid + i * 512;
                    int n = g >> 3, kq = g & 7;
                    stg[i] = *(const uint4*)(wqh + (size_t)(nt * 128 + n) * 256 + (c + 1) * 64 + kq * 8);
                }
            }
            const uint32_t bb0 = bBase + (uint32_t)(c & 1) * B_BUF;
#pragma unroll
            for (int kk8 = 0; kk8 < 4; ++kk8) {
                const int kg = c * 64 + kk8 * 16;
                uint32_t ah[2][4];
                ldsm4(ah[0], aHi + (uint32_t)kg * 2);
                ldsm4(ah[1], aHi + 16u * (LDA * 2) + (uint32_t)kg * 2);
                uint32_t bh[2][4];
                const uint32_t bb = bb0 + (uint32_t)kk8 * 32;
#pragma unroll
                for (int np = 0; np < 2; ++np)
                    ldsm4(bh[np], bb + (uint32_t)np * (16 * LDB_B));
#pragma unroll
                for (int mf = 0; mf < 2; ++mf)
#pragma unroll
                    for (int nf = 0; nf < 4; ++nf) {
                        const int np = nf >> 1, hv = (nf & 1) * 2;
                        mma16816(d[mf][nf], ah[mf], bh[np][hv], bh[np][hv + 1]);
                    }
            }
            if (c < 3) {
#pragma unroll
                for (int i = 0; i < 2; ++i) {
                    int g = tid + i * 512;
                    int n = g >> 3, kq = g & 7;
                    *(uint4*)(sb + GB_OFF + ((c + 1) & 1) * B_BUF + n * LDB_B + kq * 16) = stg[i];
                }
            }
            __syncthreads();
        }

        // ---- epilogue: bias, single-fp16 staging in dead B smem, coalesced store ----
#pragma unroll
        for (int mf = 0; mf < 2; ++mf)
#pragma unroll
            for (int h8 = 0; h8 < 2; ++h8) {
                int row = mbase + mf * 16 + h8 * 8 + qr;
#pragma unroll
                for (int nf = 0; nf < 4; ++nf) {
                    int col = nbase + nf * 8 + qc;
                    float v0 = d[mf][nf][h8 * 2]     + bias[nt * 128 + col];
                    float v1 = d[mf][nf][h8 * 2 + 1] + bias[nt * 128 + col + 1];
                    uint32_t off = (uint32_t)(row * 128 + col) * 2;
                    *(uint32_t*)(sb + GB_OFF + off) = pk(v0, v1);
                }
            }
        __syncthreads();
#pragma unroll
        for (int i = 0; i < 4; ++i) {
            int g = tid + i * 512;               // 0..2047: 128 rows x 16 uint4
            int row = g >> 4, u = g & 15;
            size_t base = (size_t)(blk * 128 + row) * 768 + nt * 128 + u * 8;
            *(uint4*)(q_out + base) = *(const uint4*)(sb + GB_OFF + row * 256 + u * 16);
        }
        __syncthreads();
    }
}

// ======================= fused attention + O-proj kernel (512 threads) ==============
// smem: Q 0 (->attn-out hi), K 33792, V 67584, attn-out lo 101376, OB 135168
#define LDQ  264
#define AQ   0
#define AK   33792
#define AV   67584
#define AOL  101376
#define OB   135168
#define AT_SMEM 172032

__global__ __launch_bounds__(512, 1)
void attn_fused(const __half* __restrict__ qkv,
                const __half* __restrict__ woh,
                const float* __restrict__ bo,
                __half* __restrict__ y_out,
                float* __restrict__ f32_out, int shifted)
{
    extern __shared__ char sb[];
    const uint32_t smb = smem_u32(sb);
    const int tid = threadIdx.x, wid = tid >> 5, lane = tid & 31;
    const int win = blockIdx.x;
    const int wh_ = (win & 63) >> 3, ww_ = win & 7;
    const int sh = shifted ? 4 : 0;

    // ---- load single-fp16 qkv: straight uint4 copies (8 threads per row) ----
    {
        const int t = tid >> 3;
        const size_t rbase = (size_t)(win * 64 + t) * 768;
#pragma unroll
        for (int i = 0; i < 12; ++i) {
            int col0 = ((tid & 7) + i * 8) * 8;      // 0..760
            int sel = col0 >> 8, c = col0 & 255;
            uint32_t bh = (sel == 0) ? AQ : (sel == 1) ? AK : AV;
            uint32_t off = (uint32_t)(t * LDQ + c) * 2;
            *(uint4*)(sb + bh + off) = *(const uint4*)(qkv + rbase + col0);
        }
    }
    __syncthreads();

    // warp task: head = wid>>1, 32-row half = wid&1
    const int head = wid >> 1;
    const int hcol = head * 32;
    const int rbase0 = (wid & 1) * 32;
    const int arow = lane & 15, acolh = (lane >> 4) * 8;
    const int grp = lane >> 3, r8 = lane & 7;
    const int b_n = r8 + ((grp & 2) << 2), b_k = (grp & 1) * 8;
    const int v_k = r8 + ((grp & 1) << 3), v_n = (grp & 2) << 2;
    const int qr = lane >> 2, qc = (lane & 3) * 2;
    const float scale = 0.17677669529663687f;

    int creg[16];
#pragma unroll
    for (int j = 0; j < 8; ++j) {
        creg[2 * j]     = regid(wh_, ww_, j * 8 + qc);
        creg[2 * j + 1] = regid(wh_, ww_, j * 8 + qc + 1);
    }

    // stream per 16-row fragment
#pragma unroll
    for (int fi = 0; fi < 2; ++fi) {
        const int rbase = rbase0 + fi * 16;
        uint32_t qf[2][4];
#pragma unroll
        for (int kt = 0; kt < 2; ++kt) {
            uint32_t off = (uint32_t)((rbase + arow) * LDQ + hcol + kt * 16 + acolh) * 2;
            ldsm4(qf[kt], smb + AQ + off);
        }

        float s[8][4];
#pragma unroll
        for (int j = 0; j < 8; ++j)
#pragma unroll
            for (int q = 0; q < 4; ++q) s[j][q] = 0.f;
#pragma unroll
        for (int kt = 0; kt < 2; ++kt)
#pragma unroll
            for (int ng = 0; ng < 4; ++ng) {
                uint32_t k4[4];
                uint32_t ka = (uint32_t)((ng * 16 + b_n) * LDQ + hcol + kt * 16 + b_k) * 2;
                ldsm4(k4, smb + AK + ka);
                mma16816(s[2 * ng],     qf[kt], k4[0], k4[1]);
                mma16816(s[2 * ng + 1], qf[kt], k4[2], k4[3]);
            }

        // scale + mask + softmax (rows rbase+qr and rbase+qr+8)
        {
            int rr0 = regid(wh_, ww_, rbase + qr);
            int rr1 = regid(wh_, ww_, rbase + qr + 8);
#pragma unroll
            for (int j = 0; j < 8; ++j) {
                s[j][0] *= scale; s[j][1] *= scale;
                s[j][2] *= scale; s[j][3] *= scale;
                if (shifted) {
                    if (creg[2 * j]     != rr0) s[j][0] += -1e9f;
                    if (creg[2 * j + 1] != rr0) s[j][1] += -1e9f;
                    if (creg[2 * j]     != rr1) s[j][2] += -1e9f;
                    if (creg[2 * j + 1] != rr1) s[j][3] += -1e9f;
                }
            }
            float m0 = -3.4e38f, m1 = -3.4e38f;
#pragma unroll
            for (int j = 0; j < 8; ++j) {
                m0 = fmaxf(m0, fmaxf(s[j][0], s[j][1]));
                m1 = fmaxf(m1, fmaxf(s[j][2], s[j][3]));
            }
            m0 = fmaxf(m0, __shfl_xor_sync(0xffffffffu, m0, 1));
            m0 = fmaxf(m0, __shfl_xor_sync(0xffffffffu, m0, 2));
            m1 = fmaxf(m1, __shfl_xor_sync(0xffffffffu, m1, 1));
            m1 = fmaxf(m1, __shfl_xor_sync(0xffffffffu, m1, 2));
            float s0 = 0.f, s1 = 0.f;
#pragma unroll
            for (int j = 0; j < 8; ++j) {
                s[j][0] = __expf(s[j][0] - m0); s0 += s[j][0];
                s[j][1] = __expf(s[j][1] - m0); s0 += s[j][1];
                s[j][2] = __expf(s[j][2] - m1); s1 += s[j][2];
                s[j][3] = __expf(s[j][3] - m1); s1 += s[j][3];
            }
            s0 += __shfl_xor_sync(0xffffffffu, s0, 1);
            s0 += __shfl_xor_sync(0xffffffffu, s0, 2);
            s1 += __shfl_xor_sync(0xffffffffu, s1, 1);
            s1 += __shfl_xor_sync(0xffffffffu, s1, 2);
            float i0 = 1.f / s0, i1 = 1.f / s1;
#pragma unroll
            for (int j = 0; j < 8; ++j) {
                s[j][0] *= i0; s[j][1] *= i0;
                s[j][2] *= i1; s[j][3] *= i1;
            }
        }

        // pack P to A-fragments (hi/lo split, registers)
        uint32_t ph[4][4], pl[4][4];
#pragma unroll
        for (int kt = 0; kt < 4; ++kt) {
            const float* e = s[2 * kt];
            const float* o2 = s[2 * kt + 1];
            float h, h2;
            h = f16rt(e[0]);  h2 = f16rt(e[1]);
            ph[kt][0] = pk(h, h2);  pl[kt][0] = pk(e[0] - h, e[1] - h2);
            h = f16rt(e[2]);  h2 = f16rt(e[3]);
            ph[kt][1] = pk(h, h2);  pl[kt][1] = pk(e[2] - h, e[3] - h2);
            h = f16rt(o2[0]); h2 = f16rt(o2[1]);
            ph[kt][2] = pk(h, h2);  pl[kt][2] = pk(o2[0] - h, o2[1] - h2);
            h = f16rt(o2[2]); h2 = f16rt(o2[3]);
            ph[kt][3] = pk(h, h2);  pl[kt][3] = pk(o2[2] - h, o2[3] - h2);
        }

        // O = P V (2-term: (Ph + Pl) x V single)
        float o[4][4];
#pragma unroll
        for (int nt = 0; nt < 4; ++nt)
#pragma unroll
            for (int q = 0; q < 4; ++q) o[nt][q] = 0.f;
#pragma unroll
        for (int kt = 0; kt < 4; ++kt)
#pragma unroll
            for (int ng = 0; ng < 2; ++ng) {
                uint32_t v4[4];
                uint32_t va = (uint32_t)((kt * 16 + v_k) * LDQ + hcol + ng * 16 + v_n) * 2;
                ldsm4t(v4, smb + AV + va);
#pragma unroll
                for (int term = 0; term < 2; ++term) {
                    const uint32_t* aa = term ? pl[kt] : ph[kt];
                    mma16816(o[2 * ng],     aa, v4[0], v4[1]);
                    mma16816(o[2 * ng + 1], aa, v4[2], v4[3]);
                }
            }

        // store attn-out split: hi -> Q area (own rows/cols), lo -> AOL area
#pragma unroll
        for (int nt = 0; nt < 4; ++nt) {
            int col = hcol + nt * 8 + qc;
            int r0 = rbase + qr;
            float v0 = o[nt][0], v1 = o[nt][1];
            float h0 = f16rt(v0), h1 = f16rt(v1);
            uint32_t off0 = (uint32_t)(r0 * LDQ + col) * 2;
            *(uint32_t*)(sb + AQ  + off0) = pk(h0, h1);
            *(uint32_t*)(sb + AOL + off0) = pk(v0 - h0, v1 - h1);
            float v2 = o[nt][2], v3 = o[nt][3];
            float h2 = f16rt(v2), h3 = f16rt(v3);
            uint32_t off1 = (uint32_t)((r0 + 8) * LDQ + col) * 2;
            *(uint32_t*)(sb + AQ  + off1) = pk(h2, h3);
            *(uint32_t*)(sb + AOL + off1) = pk(v2 - h2, v3 - h3);
        }
    }
    __syncthreads();   // attn-out complete

    // ======= O-projection (2-term): [64,256] = (Ah+Al) @ Wo^T; warp grid 2m x 8n =======
    const int mbase = (wid & 1) * 32;
    const int nbase = (wid >> 1) * 32;
    const uint32_t aX = (uint32_t)((mbase + r8 + ((grp & 1) << 3)) * LDQ + ((grp & 2) ? 8 : 0)) * 2;
    const uint32_t aHi = smb + AQ + aX;
    const uint32_t aLo = smb + AOL + aX;
    const uint32_t bBase = smb + OB + (uint32_t)((nbase + b_n) * 72 + b_k) * 2;

    float d[2][4][4];
#pragma unroll
    for (int mf = 0; mf < 2; ++mf)
#pragma unroll
        for (int nf = 0; nf < 4; ++nf)
#pragma unroll
            for (int q = 0; q < 4; ++q) d[mf][nf][q] = 0.f;

    for (int c = 0; c < 4; ++c) {
        // stage B chunk [256 n][64 k] single fp16
#pragma unroll
        for (int i = 0; i < 4; ++i) {
            int g = tid + i * 512;
            int n = g >> 3, kq = g & 7;
            uint4 v = *(const uint4*)(woh + (size_t)n * 256 + c * 64 + kq * 8);
            *(uint4*)(sb + OB + n * LDB_B + kq * 16) = v;
        }
        __syncthreads();
#pragma unroll
        for (int kk8 = 0; kk8 < 4; ++kk8) {
            const int kg = c * 64 + kk8 * 16;
            uint32_t ah[2][4], al[2][4];
            ldsm4(ah[0], aHi + (uint32_t)kg * 2);
            ldsm4(ah[1], aHi + 16u * (LDQ * 2) + (uint32_t)kg * 2);
            ldsm4(al[0], aLo + (uint32_t)kg * 2);
            ldsm4(al[1], aLo + 16u * (LDQ * 2) + (uint32_t)kg * 2);
            uint32_t bh4[2][4];
            const uint32_t bb = bBase + (uint32_t)kk8 * 32;
#pragma unroll
            for (int np = 0; np < 2; ++np)
                ldsm4(bh4[np], bb + (uint32_t)np * (16 * LDB_B));
#pragma unroll
            for (int term = 0; term < 2; ++term)
#pragma unroll
                for (int mf = 0; mf < 2; ++mf)
#pragma unroll
                    for (int nf = 0; nf < 4; ++nf) {
                        const int np = nf >> 1, hv = (nf & 1) * 2;
                        const uint32_t* aa = term ? al[mf] : ah[mf];
                        mma16816(d[mf][nf], aa, bh4[np][hv], bh4[np][hv + 1]);
                    }
        }
        __syncthreads();
    }

    if (!shifted) {
        // pass 1: stage single-fp16 y in dead B smem, then coalesced uint4 stores
#pragma unroll
        for (int mf = 0; mf < 2; ++mf)
#pragma unroll
            for (int h8 = 0; h8 < 2; ++h8) {
                int row = mbase + mf * 16 + h8 * 8 + qr;
#pragma unroll
                for (int nf = 0; nf < 4; ++nf) {
                    int col = nbase + nf * 8 + qc;
                    float v0 = d[mf][nf][h8 * 2]     + bo[col];
                    float v1 = d[mf][nf][h8 * 2 + 1] + bo[col + 1];
                    uint32_t off = (uint32_t)(row * 256 + col) * 2;
                    *(uint32_t*)(sb + OB + off) = pk(v0, v1);
                }
            }
        __syncthreads();
#pragma unroll
        for (int i = 0; i < 4; ++i) {
            int g = tid + i * 512;               // 0..2047: 64 rows x 32 uint4
            int row = g >> 5, u = g & 31;
            int tok = win * 64 + row;
            int m = tok >> 12, w = (tok >> 6) & 63, tt = tok & 63;
            int gh = (w >> 3) * 8 + (tt >> 3);
            int gw = (w & 7) * 8 + (tt & 7);
            size_t base = (size_t)((m * 64 + gh) * 64 + gw) * 256 + u * 8;
            *(uint4*)(y_out + base) = *(const uint4*)(sb + OB + row * 512 + u * 16);
        }
    } else {
        // pass 2: direct fp32 image scatter (+roll back), full-sector float2 quads
#pragma unroll
        for (int mf = 0; mf < 2; ++mf)
#pragma unroll
            for (int h8 = 0; h8 < 2; ++h8) {
                int row = mbase + mf * 16 + h8 * 8 + qr;
                int tok = win * 64 + row;
                int m = tok >> 12, w = (tok >> 6) & 63, tt = tok & 63;
                int gh = ((w >> 3) * 8 + (tt >> 3) + sh) & 63;
                int gw = ((w & 7) * 8 + (tt & 7) + sh) & 63;
                size_t base = (size_t)((m * 64 + gh) * 64 + gw) * 256;
#pragma unroll
                for (int nf = 0; nf < 4; ++nf) {
                    int col = nbase + nf * 8 + qc;
                    float v0 = d[mf][nf][h8 * 2]     + bo[col];
                    float v1 = d[mf][nf][h8 * 2 + 1] + bo[col + 1];
                    *(float2*)(f32_out + base + col) = make_float2(v0, v1);
                }
            }
    }
}

// ======================= launch =======================
extern "C" void kernel_launch(void* const* d_in, const int* in_sizes, int n_in,
                              void* d_out, int out_size) {
    (void)in_sizes; (void)n_in; (void)out_size;
    const float* x    = (const float*)d_in[0];
    const float* wqkv = (const float*)d_in[1];
    const float* bqkv = (const float*)d_in[2];
    const float* wo   = (const float*)d_in[3];
    const float* bo   = (const float*)d_in[4];
    float* out = (float*)d_out;

    cudaFuncSetAttribute(gemm_qkv,   cudaFuncAttributeMaxDynamicSharedMemorySize, GS_SMEM);
    cudaFuncSetAttribute(attn_fused, cudaFuncAttributeMaxDynamicSharedMemorySize, AT_SMEM);

    __half *wqh, *woh, *qkvp, *yv;
    cudaGetSymbolAddress((void**)&wqh,  g_wtq_h);
    cudaGetSymbolAddress((void**)&woh,  g_wto_h);
    cudaGetSymbolAddress((void**)&qkvp, g_qkv);
    cudaGetSymbolAddress((void**)&yv,   g_y);

    prep_kernel<<<1024, 256>>>(wqkv, wo);

    for (int pass = 0; pass < 2; ++pass) {
        gemm_qkv<<<1024, 512, GS_SMEM>>>(x, yv, wqh, bqkv, qkvp, pass);
        attn_fused<<<2048, 512, AT_SMEM>>>(qkvp, woh, bo, yv, out, pass);
    }
}

// round 17
// speedup vs baseline: 2.0956x; 1.0309x over previous
#include <cuda_runtime.h>
#include <cuda_fp16.h>
#include <cstdint>

// Swin layer: fp16 HMMA GEMMs + fused flash-attention + O-proj.
// R17: gemm_qkv warp tile 32x64 (CTA 128x256, 3 N-tiles) — 25% less smem
// traffic per MMA, half the syncthreads. Attention kernel unchanged.
#define NTOK 131072          // 32 * 64 * 64 tokens

// -------- device scratch (allocation-free rule) --------
__device__ __half g_qkv[(size_t)NTOK * 768];   // single fp16
__device__ __half g_y[NTOK * 256];             // pass-1 output, image layout
__device__ __half g_wtq_h[768 * 256];          // W_qkv^T [N][K], single fp16
__device__ __half g_wto_h[256 * 256];          // W_o^T   [N][K], single fp16

// ======================= helpers =======================
__device__ __forceinline__ uint32_t smem_u32(const void* p) {
    uint32_t a;
    asm("{ .reg .u64 t; cvta.to.shared.u64 t, %1; cvt.u32.u64 %0, t; }" : "=r"(a) : "l"(p));
    return a;
}
__device__ __forceinline__ void ldsm4(uint32_t r[4], uint32_t addr) {
    asm volatile("ldmatrix.sync.aligned.m8n8.x4.shared.b16 {%0,%1,%2,%3}, [%4];"
                 : "=r"(r[0]), "=r"(r[1]), "=r"(r[2]), "=r"(r[3]) : "r"(addr));
}
__device__ __forceinline__ void ldsm4t(uint32_t r[4], uint32_t addr) {
    asm volatile("ldmatrix.sync.aligned.m8n8.x4.trans.shared.b16 {%0,%1,%2,%3}, [%4];"
                 : "=r"(r[0]), "=r"(r[1]), "=r"(r[2]), "=r"(r[3]) : "r"(addr));
}
__device__ __forceinline__ void mma16816(float d[4], const uint32_t a[4],
                                         uint32_t b0, uint32_t b1) {
    asm volatile(
        "mma.sync.aligned.m16n8k16.row.col.f32.f16.f16.f32 "
        "{%0,%1,%2,%3}, {%4,%5,%6,%7}, {%8,%9}, {%0,%1,%2,%3};"
        : "+f"(d[0]), "+f"(d[1]), "+f"(d[2]), "+f"(d[3])
        : "r"(a[0]), "r"(a[1]), "r"(a[2]), "r"(a[3]), "r"(b0), "r"(b1));
}
__device__ __forceinline__ uint32_t pk(float c0, float c1) {   // f16x2(lo=c0, hi=c1)
    uint32_t d;
    asm("cvt.rn.f16x2.f32 %0, %1, %2;" : "=r"(d) : "f"(c1), "f"(c0));
    return d;
}
__device__ __forceinline__ float f16rt(float v) {
    return __half2float(__float2half_rn(v));
}
__device__ __forceinline__ int regid(int wh, int ww, int t) {
    int r = t >> 3, c = t & 7;
    int hr = (wh == 7) ? ((r < 4) ? 1 : 2) : 0;
    int wr = (ww == 7) ? ((c < 4) ? 1 : 2) : 0;
    return hr * 3 + wr;
}

// ======================= prep: W^T fp16 singles =======================
__global__ void prep_kernel(const float* __restrict__ wqkv, const float* __restrict__ wo) {
    int i = blockIdx.x * blockDim.x + threadIdx.x;
    if (i < 768 * 256) {
        int n = i >> 8, k = i & 255;
        g_wtq_h[i] = __float2half_rn(wqkv[k * 768 + n]);
    } else if (i < 768 * 256 + 256 * 256) {
        int j = i - 768 * 256;
        int n = j >> 8, k = j & 255;
        g_wto_h[j] = __float2half_rn(wo[k * 256 + n]);
    }
}

// ======================= QKV GEMM kernel (512 threads, warp tile 32x64) ==========
#define LDA      264
#define GB_OFF   67584               // A buffer: 128*264*2
#define B_BUF    36864               // one 256n x 64k fp16 chunk (stride 72)
#define LDB_B    144
#define GS_SMEM  (GB_OFF + 2 * B_BUF)   // 141312 B

__global__ __launch_bounds__(512, 1)
void gemm_qkv(const float* __restrict__ xin,
              const __half* __restrict__ y_in,
              const __half* __restrict__ wqh,
              const float* __restrict__ bias,
              __half* __restrict__ q_out,
              int shifted)
{
    extern __shared__ char sb[];
    const uint32_t smb = smem_u32(sb);
    const int tid = threadIdx.x, wid = tid >> 5, lane = tid & 31;
    const int blk = blockIdx.x;
    const int sh = shifted ? 4 : 0;

    // ---- load A (128 rows x 256), window-gather with roll, single fp16 ----
    for (int g = tid; g < 4096; g += 512) {
        int t = g >> 5;
        int col0 = (g & 31) * 8;
        int tok = blk * 128 + t;
        int m = tok >> 12, w = (tok >> 6) & 63, tt = tok & 63;
        int gh = ((w >> 3) * 8 + (tt >> 3) + sh) & 63;
        int gw = ((w & 7) * 8 + (tt & 7) + sh) & 63;
        size_t idx = (size_t)((m * 64 + gh) * 64 + gw) * 256 + col0;
        uint32_t off = ((uint32_t)t * LDA + col0) * 2;
        if (!shifted) {
            const float* sp = xin + idx;
            float4 f0 = *(const float4*)sp, f1 = *(const float4*)(sp + 4);
            uint32_t hw[4];
            hw[0] = pk(f0.x, f0.y); hw[1] = pk(f0.z, f0.w);
            hw[2] = pk(f1.x, f1.y); hw[3] = pk(f1.z, f1.w);
            *(uint4*)(sb + off) = make_uint4(hw[0], hw[1], hw[2], hw[3]);
        } else {
            *(uint4*)(sb + off) = *(const uint4*)(y_in + idx);
        }
    }

    // warp grid: 4m x 4n, warp tile 32 rows x 64 cols
    const int mbase = (wid & 3) * 32;
    const int nbase = (wid >> 2) * 64;
    const int grp = lane >> 3, r8 = lane & 7;
    const int a_row = mbase + r8 + ((grp & 1) << 3);
    const int a_kof = (grp & 2) ? 8 : 0;
    const uint32_t aHi = smb + (uint32_t)(a_row * LDA + a_kof) * 2;
    const int b_n  = r8 + ((grp & 2) << 2);
    const int b_kof = (grp & 1) ? 8 : 0;
    const uint32_t bBase = smb + GB_OFF + (uint32_t)((nbase + b_n) * 72 + b_kof) * 2;
    const int qr = lane >> 2, qc = (lane & 3) * 2;

    for (int nt = 0; nt < 3; ++nt) {
        float d[2][8][4];
#pragma unroll
        for (int mf = 0; mf < 2; ++mf)
#pragma unroll
            for (int nf = 0; nf < 8; ++nf)
#pragma unroll
                for (int q = 0; q < 4; ++q) d[mf][nf][q] = 0.f;

        // stage B chunk 0 (256n x 64k fp16, 32KB -> 2048 uint4 tasks)
#pragma unroll
        for (int i = 0; i < 4; ++i) {
            int g = tid + i * 512;
            int n = g >> 3, kq = g & 7;
            uint4 v = *(const uint4*)(wqh + (size_t)(nt * 256 + n) * 256 + kq * 8);
            *(uint4*)(sb + GB_OFF + n * LDB_B + kq * 16) = v;
        }
        __syncthreads();

        for (int c = 0; c < 4; ++c) {
            uint4 stg[4];
            if (c < 3) {
#pragma unroll
                for (int i = 0; i < 4; ++i) {
                    int g = tid + i * 512;
                    int n = g >> 3, kq = g & 7;
                    stg[i] = *(const uint4*)(wqh + (size_t)(nt * 256 + n) * 256 + (c + 1) * 64 + kq * 8);
                }
            }
            const uint32_t bb0 = bBase + (uint32_t)(c & 1) * B_BUF;
#pragma unroll
            for (int kk8 = 0; kk8 < 4; ++kk8) {
                const int kg = c * 64 + kk8 * 16;
                uint32_t ah[2][4];
                ldsm4(ah[0], aHi + (uint32_t)kg * 2);
                ldsm4(ah[1], aHi + 16u * (LDA * 2) + (uint32_t)kg * 2);
                uint32_t bh[4][4];
                const uint32_t bb = bb0 + (uint32_t)kk8 * 32;
#pragma unroll
                for (int np = 0; np < 4; ++np)
                    ldsm4(bh[np], bb + (uint32_t)np * (16 * LDB_B));
#pragma unroll
                for (int mf = 0; mf < 2; ++mf)
#pragma unroll
                    for (int nf = 0; nf < 8; ++nf) {
                        const int np = nf >> 1, hv = (nf & 1) * 2;
                        mma16816(d[mf][nf], ah[mf], bh[np][hv], bh[np][hv + 1]);
                    }
            }
            if (c < 3) {
#pragma unroll
                for (int i = 0; i < 4; ++i) {
                    int g = tid + i * 512;
                    int n = g >> 3, kq = g & 7;
                    *(uint4*)(sb + GB_OFF + ((c + 1) & 1) * B_BUF + n * LDB_B + kq * 16) = stg[i];
                }
            }
            __syncthreads();
        }

        // ---- epilogue: bias, single-fp16 staging (64KB overlays B bufs), store ----
#pragma unroll
        for (int mf = 0; mf < 2; ++mf)
#pragma unroll
            for (int h8 = 0; h8 < 2; ++h8) {
                int row = mbase + mf * 16 + h8 * 8 + qr;
#pragma unroll
                for (int nf = 0; nf < 8; ++nf) {
                    int col = nbase + nf * 8 + qc;
                    float v0 = d[mf][nf][h8 * 2]     + bias[nt * 256 + col];
                    float v1 = d[mf][nf][h8 * 2 + 1] + bias[nt * 256 + col + 1];
                    uint32_t off = (uint32_t)(row * 256 + col) * 2;
                    *(uint32_t*)(sb + GB_OFF + off) = pk(v0, v1);
                }
            }
        __syncthreads();
#pragma unroll
        for (int i = 0; i < 8; ++i) {
            int g = tid + i * 512;               // 0..4095: 128 rows x 32 uint4
            int row = g >> 5, u = g & 31;
            size_t base = (size_t)(blk * 128 + row) * 768 + nt * 256 + u * 8;
            *(uint4*)(q_out + base) = *(const uint4*)(sb + GB_OFF + row * 512 + u * 16);
        }
        __syncthreads();
    }
}

// ======================= fused attention + O-proj kernel (512 threads) ==============
// smem: Q 0 (->attn-out hi), K 33792, V 67584, attn-out lo 101376, OB 135168
#define LDQ  264
#define AQ   0
#define AK   33792
#define AV   67584
#define AOL  101376
#define OB   135168
#define AT_SMEM 172032

__global__ __launch_bounds__(512, 1)
void attn_fused(const __half* __restrict__ qkv,
                const __half* __restrict__ woh,
                const float* __restrict__ bo,
                __half* __restrict__ y_out,
                float* __restrict__ f32_out, int shifted)
{
    extern __shared__ char sb[];
    const uint32_t smb = smem_u32(sb);
    const int tid = threadIdx.x, wid = tid >> 5, lane = tid & 31;
    const int win = blockIdx.x;
    const int wh_ = (win & 63) >> 3, ww_ = win & 7;
    const int sh = shifted ? 4 : 0;

    // ---- load single-fp16 qkv: straight uint4 copies (8 threads per row) ----
    {
        const int t = tid >> 3;
        const size_t rbase = (size_t)(win * 64 + t) * 768;
#pragma unroll
        for (int i = 0; i < 12; ++i) {
            int col0 = ((tid & 7) + i * 8) * 8;      // 0..760
            int sel = col0 >> 8, c = col0 & 255;
            uint32_t bh = (sel == 0) ? AQ : (sel == 1) ? AK : AV;
            uint32_t off = (uint32_t)(t * LDQ + c) * 2;
            *(uint4*)(sb + bh + off) = *(const uint4*)(qkv + rbase + col0);
        }
    }
    __syncthreads();

    // warp task: head = wid>>1, 32-row half = wid&1
    const int head = wid >> 1;
    const int hcol = head * 32;
    const int rbase0 = (wid & 1) * 32;
    const int arow = lane & 15, acolh = (lane >> 4) * 8;
    const int grp = lane >> 3, r8 = lane & 7;
    const int b_n = r8 + ((grp & 2) << 2), b_k = (grp & 1) * 8;
    const int v_k = r8 + ((grp & 1) << 3), v_n = (grp & 2) << 2;
    const int qr = lane >> 2, qc = (lane & 3) * 2;
    const float scale = 0.17677669529663687f;

    int creg[16];
#pragma unroll
    for (int j = 0; j < 8; ++j) {
        creg[2 * j]     = regid(wh_, ww_, j * 8 + qc);
        creg[2 * j + 1] = regid(wh_, ww_, j * 8 + qc + 1);
    }

    // stream per 16-row fragment
#pragma unroll
    for (int fi = 0; fi < 2; ++fi) {
        const int rbase = rbase0 + fi * 16;
        uint32_t qf[2][4];
#pragma unroll
        for (int kt = 0; kt < 2; ++kt) {
            uint32_t off = (uint32_t)((rbase + arow) * LDQ + hcol + kt * 16 + acolh) * 2;
            ldsm4(qf[kt], smb + AQ + off);
        }

        float s[8][4];
#pragma unroll
        for (int j = 0; j < 8; ++j)
#pragma unroll
            for (int q = 0; q < 4; ++q) s[j][q] = 0.f;
#pragma unroll
        for (int kt = 0; kt < 2; ++kt)
#pragma unroll
            for (int ng = 0; ng < 4; ++ng) {
                uint32_t k4[4];
                uint32_t ka = (uint32_t)((ng * 16 + b_n) * LDQ + hcol + kt * 16 + b_k) * 2;
                ldsm4(k4, smb + AK + ka);
                mma16816(s[2 * ng],     qf[kt], k4[0], k4[1]);
                mma16816(s[2 * ng + 1], qf[kt], k4[2], k4[3]);
            }

        // scale + mask + softmax (rows rbase+qr and rbase+qr+8)
        {
            int rr0 = regid(wh_, ww_, rbase + qr);
            int rr1 = regid(wh_, ww_, rbase + qr + 8);
#pragma unroll
            for (int j = 0; j < 8; ++j) {
                s[j][0] *= scale; s[j][1] *= scale;
                s[j][2] *= scale; s[j][3] *= scale;
                if (shifted) {
                    if (creg[2 * j]     != rr0) s[j][0] += -1e9f;
                    if (creg[2 * j + 1] != rr0) s[j][1] += -1e9f;
                    if (creg[2 * j]     != rr1) s[j][2] += -1e9f;
                    if (creg[2 * j + 1] != rr1) s[j][3] += -1e9f;
                }
            }
            float m0 = -3.4e38f, m1 = -3.4e38f;
#pragma unroll
            for (int j = 0; j < 8; ++j) {
                m0 = fmaxf(m0, fmaxf(s[j][0], s[j][1]));
                m1 = fmaxf(m1, fmaxf(s[j][2], s[j][3]));
            }
            m0 = fmaxf(m0, __shfl_xor_sync(0xffffffffu, m0, 1));
            m0 = fmaxf(m0, __shfl_xor_sync(0xffffffffu, m0, 2));
            m1 = fmaxf(m1, __shfl_xor_sync(0xffffffffu, m1, 1));
            m1 = fmaxf(m1, __shfl_xor_sync(0xffffffffu, m1, 2));
            float s0 = 0.f, s1 = 0.f;
#pragma unroll
            for (int j = 0; j < 8; ++j) {
                s[j][0] = __expf(s[j][0] - m0); s0 += s[j][0];
                s[j][1] = __expf(s[j][1] - m0); s0 += s[j][1];
                s[j][2] = __expf(s[j][2] - m1); s1 += s[j][2];
                s[j][3] = __expf(s[j][3] - m1); s1 += s[j][3];
            }
            s0 += __shfl_xor_sync(0xffffffffu, s0, 1);
            s0 += __shfl_xor_sync(0xffffffffu, s0, 2);
            s1 += __shfl_xor_sync(0xffffffffu, s1, 1);
            s1 += __shfl_xor_sync(0xffffffffu, s1, 2);
            float i0 = 1.f / s0, i1 = 1.f / s1;
#pragma unroll
            for (int j = 0; j < 8; ++j) {
                s[j][0] *= i0; s[j][1] *= i0;
                s[j][2] *= i1; s[j][3] *= i1;
            }
        }

        // pack P to A-fragments (hi/lo split, registers)
        uint32_t ph[4][4], pl[4][4];
#pragma unroll
        for (int kt = 0; kt < 4; ++kt) {
            const float* e = s[2 * kt];
            const float* o2 = s[2 * kt + 1];
            float h, h2;
            h = f16rt(e[0]);  h2 = f16rt(e[1]);
            ph[kt][0] = pk(h, h2);  pl[kt][0] = pk(e[0] - h, e[1] - h2);
            h = f16rt(e[2]);  h2 = f16rt(e[3]);
            ph[kt][1] = pk(h, h2);  pl[kt][1] = pk(e[2] - h, e[3] - h2);
            h = f16rt(o2[0]); h2 = f16rt(o2[1]);
            ph[kt][2] = pk(h, h2);  pl[kt][2] = pk(o2[0] - h, o2[1] - h2);
            h = f16rt(o2[2]); h2 = f16rt(o2[3]);
            ph[kt][3] = pk(h, h2);  pl[kt][3] = pk(o2[2] - h, o2[3] - h2);
        }

        // O = P V (2-term: (Ph + Pl) x V single)
        float o[4][4];
#pragma unroll
        for (int nt = 0; nt < 4; ++nt)
#pragma unroll
            for (int q = 0; q < 4; ++q) o[nt][q] = 0.f;
#pragma unroll
        for (int kt = 0; kt < 4; ++kt)
#pragma unroll
            for (int ng = 0; ng < 2; ++ng) {
                uint32_t v4[4];
                uint32_t va = (uint32_t)((kt * 16 + v_k) * LDQ + hcol + ng * 16 + v_n) * 2;
                ldsm4t(v4, smb + AV + va);
#pragma unroll
                for (int term = 0; term < 2; ++term) {
                    const uint32_t* aa = term ? pl[kt] : ph[kt];
                    mma16816(o[2 * ng],     aa, v4[0], v4[1]);
                    mma16816(o[2 * ng + 1], aa, v4[2], v4[3]);
                }
            }

        // store attn-out split: hi -> Q area (own rows/cols), lo -> AOL area
#pragma unroll
        for (int nt = 0; nt < 4; ++nt) {
            int col = hcol + nt * 8 + qc;
            int r0 = rbase + qr;
            float v0 = o[nt][0], v1 = o[nt][1];
            float h0 = f16rt(v0), h1 = f16rt(v1);
            uint32_t off0 = (uint32_t)(r0 * LDQ + col) * 2;
            *(uint32_t*)(sb + AQ  + off0) = pk(h0, h1);
            *(uint32_t*)(sb + AOL + off0) = pk(v0 - h0, v1 - h1);
            float v2 = o[nt][2], v3 = o[nt][3];
            float h2 = f16rt(v2), h3 = f16rt(v3);
            uint32_t off1 = (uint32_t)((r0 + 8) * LDQ + col) * 2;
            *(uint32_t*)(sb + AQ  + off1) = pk(h2, h3);
            *(uint32_t*)(sb + AOL + off1) = pk(v2 - h2, v3 - h3);
        }
    }
    __syncthreads();   // attn-out complete

    // ======= O-projection (2-term): [64,256] = (Ah+Al) @ Wo^T; warp grid 2m x 8n =======
    const int mbase = (wid & 1) * 32;
    const int nbase = (wid >> 1) * 32;
    const uint32_t aX = (uint32_t)((mbase + r8 + ((grp & 1) << 3)) * LDQ + ((grp & 2) ? 8 : 0)) * 2;
    const uint32_t aHi = smb + AQ + aX;
    const uint32_t aLo = smb + AOL + aX;
    const uint32_t bBase = smb + OB + (uint32_t)((nbase + b_n) * 72 + b_k) * 2;

    float d[2][4][4];
#pragma unroll
    for (int mf = 0; mf < 2; ++mf)
#pragma unroll
        for (int nf = 0; nf < 4; ++nf)
#pragma unroll
            for (int q = 0; q < 4; ++q) d[mf][nf][q] = 0.f;

    for (int c = 0; c < 4; ++c) {
        // stage B chunk [256 n][64 k] single fp16
#pragma unroll
        for (int i = 0; i < 4; ++i) {
            int g = tid + i * 512;
            int n = g >> 3, kq = g & 7;
            uint4 v = *(const uint4*)(woh + (size_t)n * 256 + c * 64 + kq * 8);
            *(uint4*)(sb + OB + n * LDB_B + kq * 16) = v;
        }
        __syncthreads();
#pragma unroll
        for (int kk8 = 0; kk8 < 4; ++kk8) {
            const int kg = c * 64 + kk8 * 16;
            uint32_t ah[2][4], al[2][4];
            ldsm4(ah[0], aHi + (uint32_t)kg * 2);
            ldsm4(ah[1], aHi + 16u * (LDQ * 2) + (uint32_t)kg * 2);
            ldsm4(al[0], aLo + (uint32_t)kg * 2);
            ldsm4(al[1], aLo + 16u * (LDQ * 2) + (uint32_t)kg * 2);
            uint32_t bh4[2][4];
            const uint32_t bb = bBase + (uint32_t)kk8 * 32;
#pragma unroll
            for (int np = 0; np < 2; ++np)
                ldsm4(bh4[np], bb + (uint32_t)np * (16 * LDB_B));
#pragma unroll
            for (int term = 0; term < 2; ++term)
#pragma unroll
                for (int mf = 0; mf < 2; ++mf)
#pragma unroll
                    for (int nf = 0; nf < 4; ++nf) {
                        const int np = nf >> 1, hv = (nf & 1) * 2;
                        const uint32_t* aa = term ? al[mf] : ah[mf];
                        mma16816(d[mf][nf], aa, bh4[np][hv], bh4[np][hv + 1]);
                    }
        }
        __syncthreads();
    }

    if (!shifted) {
        // pass 1: stage single-fp16 y in dead B smem, then coalesced uint4 stores
#pragma unroll
        for (int mf = 0; mf < 2; ++mf)
#pragma unroll
            for (int h8 = 0; h8 < 2; ++h8) {
                int row = mbase + mf * 16 + h8 * 8 + qr;
#pragma unroll
                for (int nf = 0; nf < 4; ++nf) {
                    int col = nbase + nf * 8 + qc;
                    float v0 = d[mf][nf][h8 * 2]     + bo[col];
                    float v1 = d[mf][nf][h8 * 2 + 1] + bo[col + 1];
                    uint32_t off = (uint32_t)(row * 256 + col) * 2;
                    *(uint32_t*)(sb + OB + off) = pk(v0, v1);
                }
            }
        __syncthreads();
#pragma unroll
        for (int i = 0; i < 4; ++i) {
            int g = tid + i * 512;               // 0..2047: 64 rows x 32 uint4
            int row = g >> 5, u = g & 31;
            int tok = win * 64 + row;
            int m = tok >> 12, w = (tok >> 6) & 63, tt = tok & 63;
            int gh = (w >> 3) * 8 + (tt >> 3);
            int gw = (w & 7) * 8 + (tt & 7);
            size_t base = (size_t)((m * 64 + gh) * 64 + gw) * 256 + u * 8;
            *(uint4*)(y_out + base) = *(const uint4*)(sb + OB + row * 512 + u * 16);
        }
    } else {
        // pass 2: direct fp32 image scatter (+roll back), full-sector float2 quads
#pragma unroll
        for (int mf = 0; mf < 2; ++mf)
#pragma unroll
            for (int h8 = 0; h8 < 2; ++h8) {
                int row = mbase + mf * 16 + h8 * 8 + qr;
                int tok = win * 64 + row;
                int m = tok >> 12, w = (tok >> 6) & 63, tt = tok & 63;
                int gh = ((w >> 3) * 8 + (tt >> 3) + sh) & 63;
                int gw = ((w & 7) * 8 + (tt & 7) + sh) & 63;
                size_t base = (size_t)((m * 64 + gh) * 64 + gw) * 256;
#pragma unroll
                for (int nf = 0; nf < 4; ++nf) {
                    int col = nbase + nf * 8 + qc;
                    float v0 = d[mf][nf][h8 * 2]     + bo[col];
                    float v1 = d[mf][nf][h8 * 2 + 1] + bo[col + 1];
                    *(float2*)(f32_out + base + col) = make_float2(v0, v1);
                }
            }
    }
}

// ======================= launch =======================
extern "C" void kernel_launch(void* const* d_in, const int* in_sizes, int n_in,
                              void* d_out, int out_size) {
    (void)in_sizes; (void)n_in; (void)out_size;
    const float* x    = (const float*)d_in[0];
    const float* wqkv = (const float*)d_in[1];
    const float* bqkv = (const float*)d_in[2];
    const float* wo   = (const float*)d_in[3];
    const float* bo   = (const float*)d_in[4];
    float* out = (float*)d_out;

    cudaFuncSetAttribute(gemm_qkv,   cudaFuncAttributeMaxDynamicSharedMemorySize, GS_SMEM);
    cudaFuncSetAttribute(attn_fused, cudaFuncAttributeMaxDynamicSharedMemorySize, AT_SMEM);

    __half *wqh, *woh, *qkvp, *yv;
    cudaGetSymbolAddress((void**)&wqh,  g_wtq_h);
    cudaGetSymbolAddress((void**)&woh,  g_wto_h);
    cudaGetSymbolAddress((void**)&qkvp, g_qkv);
    cudaGetSymbolAddress((void**)&yv,   g_y);

    prep_kernel<<<1024, 256>>>(wqkv, wo);

    for (int pass = 0; pass < 2; ++pass) {
        gemm_qkv<<<1024, 512, GS_SMEM>>>(x, yv, wqh, bqkv, qkvp, pass);
        attn_fused<<<2048, 512, AT_SMEM>>>(qkvp, woh, bo, yv, out, pass);
    }
}